// round 6
// baseline (speedup 1.0000x reference)
#include <cuda_runtime.h>
#include <cuda_bf16.h>
#include <cstdint>

#define TB 4
#define TS 2048
#define TH 16
#define TD 64
#define TC 1024

// ---------------------------------------------------------------------------
// Scratch (alloc-free rule: __device__ globals)
// ---------------------------------------------------------------------------
static __device__ float g_qkv[(size_t)8192 * 3072];          // [B*S, 3*C] fp32
static __device__ float g_entpad[4];
// bf16 split operands
static __device__ __nv_bfloat16 g_xh[(size_t)8192 * 1024];
static __device__ __nv_bfloat16 g_xl[(size_t)8192 * 1024];
static __device__ __nv_bfloat16 g_wqh[(size_t)3072 * 1024];  // w_qkv^T [N,K]
static __device__ __nv_bfloat16 g_wql[(size_t)3072 * 1024];
static __device__ __nv_bfloat16 g_ch[(size_t)8192 * 1024];   // attn out hi
static __device__ __nv_bfloat16 g_cl[(size_t)8192 * 1024];   // attn out lo
static __device__ __nv_bfloat16 g_wph[(size_t)1024 * 1024];  // w_proj^T [N,K]
static __device__ __nv_bfloat16 g_wpl[(size_t)1024 * 1024];

// ---------------------------------------------------------------------------
// Helpers (sm_103 base target: ldmatrix + mma.sync + cp.async only)
// ---------------------------------------------------------------------------
__device__ __forceinline__ uint32_t smem_u32(const void* p) {
    uint32_t a;
    asm("{ .reg .u64 t; cvta.to.shared.u64 t, %1; cvt.u32.u64 %0, t; }" : "=r"(a) : "l"(p));
    return a;
}
__device__ __forceinline__ uint32_t sw128(uint32_t off) { return off ^ ((off >> 3) & 0x70); }

__device__ __forceinline__ void cp16(uint32_t saddr, const void* gptr) {
    asm volatile("cp.async.cg.shared.global [%0], [%1], 16;" :: "r"(saddr), "l"(gptr));
}
__device__ __forceinline__ void cp_commit() {
    asm volatile("cp.async.commit_group;" ::: "memory");
}
template <int N>
__device__ __forceinline__ void cp_wait() {
    asm volatile("cp.async.wait_group %0;" :: "n"(N) : "memory");
}

__device__ __forceinline__ void ldm_x4(uint32_t addr, uint32_t r[4]) {
    asm volatile("ldmatrix.sync.aligned.m8n8.x4.shared.b16 {%0,%1,%2,%3}, [%4];"
                 : "=r"(r[0]), "=r"(r[1]), "=r"(r[2]), "=r"(r[3]) : "r"(addr));
}
__device__ __forceinline__ void ldm_x4_t(uint32_t addr, uint32_t r[4]) {
    asm volatile("ldmatrix.sync.aligned.m8n8.x4.trans.shared.b16 {%0,%1,%2,%3}, [%4];"
                 : "=r"(r[0]), "=r"(r[1]), "=r"(r[2]), "=r"(r[3]) : "r"(addr));
}

__device__ __forceinline__ void mma16816(float d[4], const uint32_t a[4], const uint32_t b[2]) {
    asm volatile(
        "mma.sync.aligned.m16n8k16.row.col.f32.bf16.bf16.f32 "
        "{%0,%1,%2,%3}, {%4,%5,%6,%7}, {%8,%9}, {%0,%1,%2,%3};"
        : "+f"(d[0]), "+f"(d[1]), "+f"(d[2]), "+f"(d[3])
        : "r"(a[0]), "r"(a[1]), "r"(a[2]), "r"(a[3]), "r"(b[0]), "r"(b[1]));
}

// split two floats into packed bf16x2 hi + lo halves (hi.x = first)
__device__ __forceinline__ void split2(float a, float b, uint32_t& hi, uint32_t& lo) {
    __nv_bfloat162 h = __floats2bfloat162_rn(a, b);
    float ra = a - __bfloat162float(h.x);
    float rb = b - __bfloat162float(h.y);
    __nv_bfloat162 l = __floats2bfloat162_rn(ra, rb);
    hi = *(uint32_t*)&h;
    lo = *(uint32_t*)&l;
}

// ---------------------------------------------------------------------------
// Split-precision conversion kernels
// ---------------------------------------------------------------------------
__device__ __forceinline__ void split_one(float v, __nv_bfloat16& h, __nv_bfloat16& l) {
    h = __float2bfloat16_rn(v);
    l = __float2bfloat16_rn(v - __bfloat162float(h));
}

__global__ __launch_bounds__(256) void split_kernel(
    const float4* __restrict__ in, __nv_bfloat16* __restrict__ hi,
    __nv_bfloat16* __restrict__ lo, int n4)
{
    int i = blockIdx.x * 256 + threadIdx.x;
    if (i >= n4) return;
    float4 v = in[i];
    uint32_t h01, h23, l01, l23;
    split2(v.x, v.y, h01, l01);
    split2(v.z, v.w, h23, l23);
    ((uint2*)hi)[i] = make_uint2(h01, h23);
    ((uint2*)lo)[i] = make_uint2(l01, l23);
}

// Transpose + split: in f32 [K,N] -> hi/lo bf16 [N,K]
__global__ __launch_bounds__(256) void splitT_kernel(
    const float* __restrict__ in, __nv_bfloat16* __restrict__ hi,
    __nv_bfloat16* __restrict__ lo, int K, int N)
{
    __shared__ float t[32][33];
    const int n0 = blockIdx.x << 5;
    const int k0 = blockIdx.y << 5;
    const int tx = threadIdx.x, ty = threadIdx.y;   // 32 x 8
#pragma unroll
    for (int j = 0; j < 32; j += 8)
        t[ty + j][tx] = in[(size_t)(k0 + ty + j) * N + n0 + tx];
    __syncthreads();
#pragma unroll
    for (int j = 0; j < 32; j += 8) {
        float v = t[tx][ty + j];
        __nv_bfloat16 h, l;
        split_one(v, h, l);
        size_t o = (size_t)(n0 + ty + j) * K + k0 + tx;
        hi[o] = h;
        lo[o] = l;
    }
}

// ---------------------------------------------------------------------------
// Warp-MMA bf16x3 GEMM: C[M,N] = A[M,K] @ Bt[N,K]^T
// ---------------------------------------------------------------------------
#define GSM_AH 0
#define GSM_AL 16384
#define GSM_BH 32768
#define GSM_BL 49152
#define GSM_BUF 65536
#define GEMM_SMEM (2 * GSM_BUF)

__global__ __launch_bounds__(256) void gemm_mma_kernel(
    const __nv_bfloat16* __restrict__ Ah, const __nv_bfloat16* __restrict__ Al,
    const __nv_bfloat16* __restrict__ Bh, const __nv_bfloat16* __restrict__ Bl,
    float* __restrict__ C, int M, int N, int K)
{
    extern __shared__ char smem[];
    const uint32_t sb = smem_u32(smem);
    const int tid = threadIdx.x;
    const int wid = tid >> 5;
    const int lane = tid & 31;
    const int row0 = blockIdx.y << 7;
    const int col0 = blockIdx.x << 7;
    const int wm = (wid & 1) << 6;
    const int wn = (wid >> 1) << 5;

    const int lr0 = tid >> 1;
    const int lk0 = (tid & 1) << 2;

    float acc[4][4][4];
#pragma unroll
    for (int mt = 0; mt < 4; ++mt)
#pragma unroll
        for (int nt = 0; nt < 4; ++nt)
#pragma unroll
            for (int r = 0; r < 4; ++r) acc[mt][nt][r] = 0.f;

    const int nk = K >> 6;

    auto load_tile = [&](int kb, int buf) {
        const uint32_t s0 = sb + buf * GSM_BUF;
#pragma unroll
        for (int cc = 0; cc < 4; ++cc) {
            const int r = lr0;
            const int k8 = lk0 + cc;
            const size_t offA = (size_t)(row0 + r) * K + kb + (k8 << 3);
            const size_t offB = (size_t)(col0 + r) * K + kb + (k8 << 3);
            const uint32_t so = sw128((uint32_t)((r << 7) + (k8 << 4)));
            cp16(s0 + GSM_AH + so, Ah + offA);
            cp16(s0 + GSM_AL + so, Al + offA);
            cp16(s0 + GSM_BH + so, Bh + offB);
            cp16(s0 + GSM_BL + so, Bl + offB);
        }
        cp_commit();
    };

    load_tile(0, 0);

    const int la_r = lane & 15;
    const int la_c = lane >> 4;
    const int lb_r = ((lane >> 4) << 3) + (lane & 7);
    const int lb_c = (lane >> 3) & 1;

    for (int it = 0; it < nk; ++it) {
        if (it + 1 < nk) { load_tile((it + 1) << 6, (it + 1) & 1); cp_wait<1>(); }
        else             { cp_wait<0>(); }
        __syncthreads();
        const uint32_t s0 = sb + (it & 1) * GSM_BUF;

#pragma unroll
        for (int ks = 0; ks < 4; ++ks) {
            uint32_t ah[4][4], al[4][4], bh[2][4], bl[2][4];
#pragma unroll
            for (int mt = 0; mt < 4; ++mt) {
                const uint32_t so =
                    sw128((uint32_t)(((wm + (mt << 4) + la_r) << 7) + (((ks << 1) + la_c) << 4)));
                ldm_x4(s0 + GSM_AH + so, ah[mt]);
                ldm_x4(s0 + GSM_AL + so, al[mt]);
            }
#pragma unroll
            for (int p = 0; p < 2; ++p) {
                const uint32_t so =
                    sw128((uint32_t)(((wn + (p << 4) + lb_r) << 7) + (((ks << 1) + lb_c) << 4)));
                ldm_x4(s0 + GSM_BH + so, bh[p]);
                ldm_x4(s0 + GSM_BL + so, bl[p]);
            }
#pragma unroll
            for (int mt = 0; mt < 4; ++mt)
#pragma unroll
                for (int nt = 0; nt < 4; ++nt) {
                    const uint32_t* bhp = &bh[nt >> 1][(nt & 1) << 1];
                    const uint32_t* blp = &bl[nt >> 1][(nt & 1) << 1];
                    mma16816(acc[mt][nt], ah[mt], bhp);
                    mma16816(acc[mt][nt], ah[mt], blp);
                    mma16816(acc[mt][nt], al[mt], bhp);
                }
        }
        __syncthreads();
    }

    const int g = lane >> 2, tg = lane & 3;
#pragma unroll
    for (int mt = 0; mt < 4; ++mt)
#pragma unroll
        for (int nt = 0; nt < 4; ++nt) {
            const int row = row0 + wm + (mt << 4) + g;
            const int col = col0 + wn + (nt << 3) + (tg << 1);
            *(float2*)(C + (size_t)row * N + col) = make_float2(acc[mt][nt][0], acc[mt][nt][1]);
            *(float2*)(C + (size_t)(row + 8) * N + col) = make_float2(acc[mt][nt][2], acc[mt][nt][3]);
        }
}

// ---------------------------------------------------------------------------
// LayerNorm over head_dim=64 for q and k slices of qkv, in place.
// ---------------------------------------------------------------------------
__global__ __launch_bounds__(256) void ln_kernel(
    float* __restrict__ qkv,
    const float* __restrict__ qs, const float* __restrict__ qb,
    const float* __restrict__ ks, const float* __restrict__ kb)
{
    const int w = (int)((blockIdx.x * 256u + threadIdx.x) >> 5);
    const int lane = threadIdx.x & 31;
    const int NQ = TB * TS * TH;
    if (w >= 2 * NQ) return;
    const bool isK = w >= NQ;
    const int r = isK ? (w - NQ) : w;
    const int h = r & 15;
    const int bs = r >> 4;
    float* p = qkv + (size_t)bs * 3072 + (isK ? 1024 : 0) + h * 64 + lane * 2;
    const float* sc = (isK ? ks : qs) + lane * 2;
    const float* bi = (isK ? kb : qb) + lane * 2;

    float2 v = *(const float2*)p;
    float s = v.x + v.y;
    float sq = v.x * v.x + v.y * v.y;
#pragma unroll
    for (int off = 16; off; off >>= 1) {
        s  += __shfl_xor_sync(0xffffffffu, s, off);
        sq += __shfl_xor_sync(0xffffffffu, sq, off);
    }
    float mean = s * (1.f / 64.f);
    float var = fmaxf(sq * (1.f / 64.f) - mean * mean, 0.f);
    float rstd = rsqrtf(var + 1e-5f);
    float2 o;
    o.x = (v.x - mean) * rstd * sc[0] + bi[0];
    o.y = (v.y - mean) * rstd * sc[1] + bi[1];
    *(float2*)p = o;
}

__global__ void zero4_kernel(float* p) { p[threadIdx.x] = 0.f; }

// ---------------------------------------------------------------------------
// Flash attention on mma.sync (bf16x3) + streaming entropy.
// CTA: 64 q-rows, 4 warps (warp = m16 x n64), 128 threads. K-tile = 64 keys.
// Pipeline: cp.async prefetches next tile's RAW fp32 K/V (32KB) into smem while
// current tile computes; tile top = wait -> split raw->bf16 smem -> compute.
// Smem: bf16 KH/KL/VH/VL (32KB) + raw K/V (32KB) = 64KB dynamic.
// Epilogue writes bf16 hi/lo (ch, cl) directly -> feeds proj GEMM, no split pass.
// ---------------------------------------------------------------------------
#define ASM_KH 0
#define ASM_KL 8192
#define ASM_VH 16384
#define ASM_VL 24576
#define ASM_RK 32768
#define ASM_RV 49152
#define ATTN_SMEM 65536

__global__ __launch_bounds__(128) void attn_mma_kernel(
    const float* __restrict__ qkv,
    __nv_bfloat16* __restrict__ ch, __nv_bfloat16* __restrict__ cl,
    float* __restrict__ ent)
{
    extern __shared__ char smA[];
    __shared__ float red[4];
    const uint32_t sb = smem_u32(smA);

    const int tid = threadIdx.x, wid = tid >> 5, lane = tid & 31;
    const int qb0 = blockIdx.x << 6;           // 64 q rows per CTA
    const int h = blockIdx.y, b = blockIdx.z;
    const size_t base = (size_t)b * TS * 3072 + h * 64;
    const float inv = 0.125f;                  // 1/sqrt(64), TEMP=1

    // ---- prefetch tile 0 raw K/V via cp.async (overlaps Q staging) ----
    auto prefetch_raw = [&](int kt) {
#pragma unroll
        for (int j = 0; j < 8; ++j) {
            int i = tid + 128 * j;             // 1024 (row,c4) pairs
            int row = i >> 4, c4 = i & 15;
            const float* gp = qkv + base + (size_t)(kt * 64 + row) * 3072 + c4 * 4;
            uint32_t so = (uint32_t)(row * 256 + c4 * 16);
            cp16(sb + ASM_RK + so, gp + 1024);
            cp16(sb + ASM_RV + so, gp + 2048);
        }
        cp_commit();
    };
    prefetch_raw(0);

    // ---- stage Q (scaled+split) into bf16 region [KH]=hi, [KL]=lo ----
#pragma unroll
    for (int j = 0; j < 8; ++j) {
        int i = tid + 128 * j;                 // 1024 float4 total
        int row = i >> 4, c4 = i & 15;
        float4 v = *(const float4*)(qkv + base + (size_t)(qb0 + row) * 3072 + c4 * 4);
        uint32_t h01, h23, l01, l23;
        split2(v.x * inv, v.y * inv, h01, l01);
        split2(v.z * inv, v.w * inv, h23, l23);
        uint32_t so = sw128((uint32_t)(row * 128 + c4 * 8));
        *(uint2*)(smA + ASM_KH + so) = make_uint2(h01, h23);
        *(uint2*)(smA + ASM_KL + so) = make_uint2(l01, l23);
    }
    __syncthreads();

    // ---- load Q A-fragments (hi/lo) for 4 k16 steps ----
    uint32_t qh[4][4], ql[4][4];
    {
        const int row = (wid << 4) + (lane & 15);
        const int cb = (lane >> 4) << 4;       // 0 or 16 bytes (k-half)
#pragma unroll
        for (int s = 0; s < 4; ++s) {
            uint32_t so = sw128((uint32_t)(row * 128 + s * 32 + cb));
            ldm_x4(sb + ASM_KH + so, qh[s]);
            ldm_x4(sb + ASM_KL + so, ql[s]);
        }
    }

    float o[8][4];
#pragma unroll
    for (int nt = 0; nt < 8; ++nt)
#pragma unroll
        for (int r = 0; r < 4; ++r) o[nt][r] = 0.f;
    float m2[2] = {-1e30f, -1e30f}, l2[2] = {0.f, 0.f}, T2[2] = {0.f, 0.f};

    const int kb_row = ((lane >> 4) << 3) + (lane & 7);   // K b-frag row-in-16
    const int kb_c = (lane >> 3) & 1;                     // K b-frag k-half
    const int v_key = (((lane >> 3) & 1) << 3) + (lane & 7);  // V trans key-in-16
    const int v_d = (lane >> 4) << 3;                     // V trans d offset

    for (int kt = 0; kt < TS / 64; ++kt) {
        cp_wait<0>();
        __syncthreads();   // raw ready; prev compute done reading bf16 bufs

        // ---- split raw fp32 -> bf16 hi/lo smem (swizzled) ----
#pragma unroll
        for (int j = 0; j < 8; ++j) {
            int i = tid + 128 * j;
            int row = i >> 4, c4 = i & 15;
            uint32_t ro = (uint32_t)(row * 256 + c4 * 16);
            float4 kv = *(const float4*)(smA + ASM_RK + ro);
            float4 vv = *(const float4*)(smA + ASM_RV + ro);
            uint32_t so = sw128((uint32_t)(row * 128 + c4 * 8));
            uint32_t h01, h23, l01, l23;
            split2(kv.x, kv.y, h01, l01);
            split2(kv.z, kv.w, h23, l23);
            *(uint2*)(smA + ASM_KH + so) = make_uint2(h01, h23);
            *(uint2*)(smA + ASM_KL + so) = make_uint2(l01, l23);
            split2(vv.x, vv.y, h01, l01);
            split2(vv.z, vv.w, h23, l23);
            *(uint2*)(smA + ASM_VH + so) = make_uint2(h01, h23);
            *(uint2*)(smA + ASM_VL + so) = make_uint2(l01, l23);
        }
        __syncthreads();   // raw fully consumed; bf16 bufs ready

        // ---- prefetch next tile's raw (overlaps compute below) ----
        if (kt + 1 < TS / 64) prefetch_raw(kt + 1);

        // ---- S = Q K^T (bf16x3) ----
        float s4[8][4];
#pragma unroll
        for (int nt = 0; nt < 8; ++nt)
#pragma unroll
            for (int r = 0; r < 4; ++r) s4[nt][r] = 0.f;

#pragma unroll
        for (int s = 0; s < 4; ++s) {
            uint32_t kbh[4][4], kbl[4][4];
#pragma unroll
            for (int p = 0; p < 4; ++p) {
                uint32_t so = sw128((uint32_t)(((p << 4) + kb_row) * 128 + s * 32 + kb_c * 16));
                ldm_x4(sb + ASM_KH + so, kbh[p]);
                ldm_x4(sb + ASM_KL + so, kbl[p]);
            }
#pragma unroll
            for (int nt = 0; nt < 8; ++nt) {
                const uint32_t* bh2 = &kbh[nt >> 1][(nt & 1) << 1];
                const uint32_t* bl2 = &kbl[nt >> 1][(nt & 1) << 1];
                mma16816(s4[nt], qh[s], bh2);
                mma16816(s4[nt], qh[s], bl2);
                mma16816(s4[nt], ql[s], bh2);
            }
        }

        // ---- online softmax + entropy terms (rows g, g+8 per thread) ----
        float mx0 = s4[0][0], mx1 = s4[0][2];
#pragma unroll
        for (int nt = 0; nt < 8; ++nt) {
            mx0 = fmaxf(mx0, fmaxf(s4[nt][0], s4[nt][1]));
            mx1 = fmaxf(mx1, fmaxf(s4[nt][2], s4[nt][3]));
        }
#pragma unroll
        for (int off = 1; off <= 2; off <<= 1) {
            mx0 = fmaxf(mx0, __shfl_xor_sync(0xffffffffu, mx0, off));
            mx1 = fmaxf(mx1, __shfl_xor_sync(0xffffffffu, mx1, off));
        }
        float mn0 = fmaxf(m2[0], mx0), mn1 = fmaxf(m2[1], mx1);
        float ls0 = 0.f, ts0 = 0.f, ls1 = 0.f, ts1 = 0.f;
#pragma unroll
        for (int nt = 0; nt < 8; ++nt) {
            float d0 = s4[nt][0] - mn0, d1 = s4[nt][1] - mn0;
            float d2 = s4[nt][2] - mn1, d3 = s4[nt][3] - mn1;
            float e0 = __expf(d0), e1 = __expf(d1), e2 = __expf(d2), e3 = __expf(d3);
            s4[nt][0] = e0; s4[nt][1] = e1; s4[nt][2] = e2; s4[nt][3] = e3;
            ls0 += e0 + e1; ls1 += e2 + e3;
            ts0 = fmaf(e0, d0, fmaf(e1, d1, ts0));
            ts1 = fmaf(e2, d2, fmaf(e3, d3, ts1));
        }
#pragma unroll
        for (int off = 1; off <= 2; off <<= 1) {
            ls0 += __shfl_xor_sync(0xffffffffu, ls0, off);
            ts0 += __shfl_xor_sync(0xffffffffu, ts0, off);
            ls1 += __shfl_xor_sync(0xffffffffu, ls1, off);
            ts1 += __shfl_xor_sync(0xffffffffu, ts1, off);
        }
        float dm0 = mn0 - m2[0], c0 = __expf(-dm0);
        float dm1 = mn1 - m2[1], c1 = __expf(-dm1);
        T2[0] = fmaf(c0, T2[0] - dm0 * l2[0], ts0);
        T2[1] = fmaf(c1, T2[1] - dm1 * l2[1], ts1);
        l2[0] = fmaf(l2[0], c0, ls0);
        l2[1] = fmaf(l2[1], c1, ls1);
        m2[0] = mn0; m2[1] = mn1;
#pragma unroll
        for (int nt = 0; nt < 8; ++nt) {
            o[nt][0] *= c0; o[nt][1] *= c0;
            o[nt][2] *= c1; o[nt][3] *= c1;
        }

        // ---- O += P V (bf16x3; P from frags, V via ldmatrix.trans) ----
#pragma unroll
        for (int s = 0; s < 4; ++s) {
            uint32_t pah[4], pal[4];
            split2(s4[2 * s][0],     s4[2 * s][1],     pah[0], pal[0]);
            split2(s4[2 * s][2],     s4[2 * s][3],     pah[1], pal[1]);
            split2(s4[2 * s + 1][0], s4[2 * s + 1][1], pah[2], pal[2]);
            split2(s4[2 * s + 1][2], s4[2 * s + 1][3], pah[3], pal[3]);
            uint32_t vbh[4][4], vbl[4][4];
#pragma unroll
            for (int p2 = 0; p2 < 4; ++p2) {
                uint32_t so = sw128((uint32_t)(((s << 4) + v_key) * 128 + ((p2 << 4) + v_d) * 2));
                ldm_x4_t(sb + ASM_VH + so, vbh[p2]);
                ldm_x4_t(sb + ASM_VL + so, vbl[p2]);
            }
#pragma unroll
            for (int nt = 0; nt < 8; ++nt) {
                const uint32_t* bh2 = &vbh[nt >> 1][(nt & 1) << 1];
                const uint32_t* bl2 = &vbl[nt >> 1][(nt & 1) << 1];
                mma16816(o[nt], pah, bh2);
                mma16816(o[nt], pah, bl2);
                mma16816(o[nt], pal, bh2);
            }
        }
    }

    // ---- write context directly as bf16 hi/lo (feeds proj GEMM) ----
    {
        float rl0 = 1.f / l2[0], rl1 = 1.f / l2[1];
        const int r0 = qb0 + (wid << 4) + (lane >> 2);
        const int cb = (h << 6) + ((lane & 3) << 1);
#pragma unroll
        for (int nt = 0; nt < 8; ++nt) {
            const int col = cb + (nt << 3);
            const size_t i0 = ((size_t)(b * TS + r0) * 1024 + col) >> 1;
            const size_t i1 = ((size_t)(b * TS + r0 + 8) * 1024 + col) >> 1;
            uint32_t hp, lp;
            split2(o[nt][0] * rl0, o[nt][1] * rl0, hp, lp);
            ((uint32_t*)ch)[i0] = hp;
            ((uint32_t*)cl)[i0] = lp;
            split2(o[nt][2] * rl1, o[nt][3] * rl1, hp, lp);
            ((uint32_t*)ch)[i1] = hp;
            ((uint32_t*)cl)[i1] = lp;
        }
    }

    // ---- entropy: per-row log(l) - T/l, reduce, one atomic per CTA ----
    float e = 0.f;
    if ((lane & 3) == 0)
        e = (__logf(l2[0]) - T2[0] / l2[0]) + (__logf(l2[1]) - T2[1] / l2[1]);
#pragma unroll
    for (int off = 16; off; off >>= 1) e += __shfl_xor_sync(0xffffffffu, e, off);
    if (lane == 0) red[wid] = e;
    __syncthreads();
    if (tid == 0) {
        float esum = red[0] + red[1] + red[2] + red[3];
        const float ent_scale = (float)(1.0 / (7.6246189861593985 * (double)(TH * TS)));
        atomicAdd(ent + b, esum * ent_scale);
    }
}

// ---------------------------------------------------------------------------
extern "C" void kernel_launch(void* const* d_in, const int* in_sizes, int n_in,
                              void* d_out, int out_size)
{
    const float* x       = (const float*)d_in[0];
    const float* w_qkv   = (const float*)d_in[1];
    const float* w_proj  = (const float*)d_in[2];
    const float* q_scale = (const float*)d_in[3];
    const float* q_bias  = (const float*)d_in[4];
    const float* k_scale = (const float*)d_in[5];
    const float* k_bias  = (const float*)d_in[6];
    float* out = (float*)d_out;

    float *qkv, *entpad;
    cudaGetSymbolAddress((void**)&qkv, g_qkv);
    cudaGetSymbolAddress((void**)&entpad, g_entpad);
    __nv_bfloat16 *xh, *xl, *wqh, *wql, *ch, *cl, *wph, *wpl;
    cudaGetSymbolAddress((void**)&xh, g_xh);
    cudaGetSymbolAddress((void**)&xl, g_xl);
    cudaGetSymbolAddress((void**)&wqh, g_wqh);
    cudaGetSymbolAddress((void**)&wql, g_wql);
    cudaGetSymbolAddress((void**)&ch, g_ch);
    cudaGetSymbolAddress((void**)&cl, g_cl);
    cudaGetSymbolAddress((void**)&wph, g_wph);
    cudaGetSymbolAddress((void**)&wpl, g_wpl);

    cudaFuncSetAttribute(gemm_mma_kernel, cudaFuncAttributeMaxDynamicSharedMemorySize, GEMM_SMEM);
    cudaFuncSetAttribute(attn_mma_kernel, cudaFuncAttributeMaxDynamicSharedMemorySize, ATTN_SMEM);

    const int BS = TB * TS;                 // 8192
    const size_t main_elems = (size_t)BS * TC;
    float* ent = (out_size >= (int)(main_elems + TB)) ? (out + main_elems) : entpad;

    // 1) split x -> bf16 hi/lo ; transpose+split w_qkv
    {
        int n4 = (BS * TC) / 4;
        split_kernel<<<(n4 + 255) / 256, 256>>>((const float4*)x, xh, xl, n4);
        splitT_kernel<<<dim3(3 * TC / 32, TC / 32), dim3(32, 8)>>>(w_qkv, wqh, wql, TC, 3 * TC);
    }

    // 2) QKV projection on tensor cores (mma.sync): [8192,1024] @ [1024,3072]
    gemm_mma_kernel<<<dim3(3 * TC / 128, BS / 128), 256, GEMM_SMEM>>>(
        xh, xl, wqh, wql, qkv, BS, 3 * TC, TC);

    // 3) LayerNorm q,k
    ln_kernel<<<(2 * TB * TS * TH) / 8, 256>>>(qkv, q_scale, q_bias, k_scale, k_bias);

    // 4) zero entropy accumulators
    zero4_kernel<<<1, TB>>>(ent);

    // 5) fused attention + entropy -> ch/cl bf16 (tensor-core, cp.async pipelined)
    attn_mma_kernel<<<dim3(TS / 64, TH, TB), 128, ATTN_SMEM>>>(qkv, ch, cl, ent);

    // 6) transpose+split w_proj (ctx split fused into attention epilogue)
    splitT_kernel<<<dim3(TC / 32, TC / 32), dim3(32, 8)>>>(w_proj, wph, wpl, TC, TC);

    // 7) output projection on tensor cores: [8192,1024] @ [1024,1024]
    gemm_mma_kernel<<<dim3(TC / 128, BS / 128), 256, GEMM_SMEM>>>(
        ch, cl, wph, wpl, out, BS, TC, TC);
}

// round 7
// speedup vs baseline: 1.0932x; 1.0932x over previous
#include <cuda_runtime.h>
#include <cuda_bf16.h>
#include <cstdint>

#define TB 4
#define TS 2048
#define TH 16
#define TD 64
#define TC 1024

// ---------------------------------------------------------------------------
// Scratch (alloc-free rule: __device__ globals)
// ---------------------------------------------------------------------------
static __device__ float g_qkv[(size_t)8192 * 3072];          // [B*S, 3*C] fp32
static __device__ float g_ctx[(size_t)8192 * 1024];          // [B*S, C]   fp32
static __device__ float g_entpad[4];
// bf16 split operands (GEMM)
static __device__ __nv_bfloat16 g_xh[(size_t)8192 * 1024];
static __device__ __nv_bfloat16 g_xl[(size_t)8192 * 1024];
static __device__ __nv_bfloat16 g_wqh[(size_t)3072 * 1024];  // w_qkv^T [N,K]
static __device__ __nv_bfloat16 g_wql[(size_t)3072 * 1024];
static __device__ __nv_bfloat16 g_ch[(size_t)8192 * 1024];
static __device__ __nv_bfloat16 g_cl[(size_t)8192 * 1024];
static __device__ __nv_bfloat16 g_wph[(size_t)1024 * 1024];  // w_proj^T [N,K]
static __device__ __nv_bfloat16 g_wpl[(size_t)1024 * 1024];
// pre-split attention operands, [b,h,s,d] layout (contiguous 64-elem rows)
#define NBH ((size_t)TB * TH * TS * 64)
static __device__ __nv_bfloat16 g_qh2[NBH];
static __device__ __nv_bfloat16 g_ql2[NBH];
static __device__ __nv_bfloat16 g_kh2[NBH];
static __device__ __nv_bfloat16 g_kl2[NBH];
static __device__ __nv_bfloat16 g_vh2[NBH];
static __device__ __nv_bfloat16 g_vl2[NBH];

// ---------------------------------------------------------------------------
// Helpers (sm_103 base target: ldmatrix + mma.sync + cp.async only)
// ---------------------------------------------------------------------------
__device__ __forceinline__ uint32_t smem_u32(const void* p) {
    uint32_t a;
    asm("{ .reg .u64 t; cvta.to.shared.u64 t, %1; cvt.u32.u64 %0, t; }" : "=r"(a) : "l"(p));
    return a;
}
__device__ __forceinline__ uint32_t sw128(uint32_t off) { return off ^ ((off >> 3) & 0x70); }

__device__ __forceinline__ void cp16(uint32_t saddr, const void* gptr) {
    asm volatile("cp.async.cg.shared.global [%0], [%1], 16;" :: "r"(saddr), "l"(gptr));
}
__device__ __forceinline__ void cp_commit() {
    asm volatile("cp.async.commit_group;" ::: "memory");
}
template <int N>
__device__ __forceinline__ void cp_wait() {
    asm volatile("cp.async.wait_group %0;" :: "n"(N) : "memory");
}

__device__ __forceinline__ void ldm_x4(uint32_t addr, uint32_t r[4]) {
    asm volatile("ldmatrix.sync.aligned.m8n8.x4.shared.b16 {%0,%1,%2,%3}, [%4];"
                 : "=r"(r[0]), "=r"(r[1]), "=r"(r[2]), "=r"(r[3]) : "r"(addr));
}
__device__ __forceinline__ void ldm_x4_t(uint32_t addr, uint32_t r[4]) {
    asm volatile("ldmatrix.sync.aligned.m8n8.x4.trans.shared.b16 {%0,%1,%2,%3}, [%4];"
                 : "=r"(r[0]), "=r"(r[1]), "=r"(r[2]), "=r"(r[3]) : "r"(addr));
}

__device__ __forceinline__ void mma16816(float d[4], const uint32_t a[4], const uint32_t b[2]) {
    asm volatile(
        "mma.sync.aligned.m16n8k16.row.col.f32.bf16.bf16.f32 "
        "{%0,%1,%2,%3}, {%4,%5,%6,%7}, {%8,%9}, {%0,%1,%2,%3};"
        : "+f"(d[0]), "+f"(d[1]), "+f"(d[2]), "+f"(d[3])
        : "r"(a[0]), "r"(a[1]), "r"(a[2]), "r"(a[3]), "r"(b[0]), "r"(b[1]));
}

// split two floats into packed bf16x2 hi + lo halves (hi.x = first)
__device__ __forceinline__ void split2(float a, float b, uint32_t& hi, uint32_t& lo) {
    __nv_bfloat162 h = __floats2bfloat162_rn(a, b);
    float ra = a - __bfloat162float(h.x);
    float rb = b - __bfloat162float(h.y);
    __nv_bfloat162 l = __floats2bfloat162_rn(ra, rb);
    hi = *(uint32_t*)&h;
    lo = *(uint32_t*)&l;
}

// ---------------------------------------------------------------------------
// Split-precision conversion kernels
// ---------------------------------------------------------------------------
__device__ __forceinline__ void split_one(float v, __nv_bfloat16& h, __nv_bfloat16& l) {
    h = __float2bfloat16_rn(v);
    l = __float2bfloat16_rn(v - __bfloat162float(h));
}

__global__ __launch_bounds__(256) void split_kernel(
    const float4* __restrict__ in, __nv_bfloat16* __restrict__ hi,
    __nv_bfloat16* __restrict__ lo, int n4)
{
    int i = blockIdx.x * 256 + threadIdx.x;
    if (i >= n4) return;
    float4 v = in[i];
    uint32_t h01, h23, l01, l23;
    split2(v.x, v.y, h01, l01);
    split2(v.z, v.w, h23, l23);
    ((uint2*)hi)[i] = make_uint2(h01, h23);
    ((uint2*)lo)[i] = make_uint2(l01, l23);
}

// Transpose + split: in f32 [K,N] -> hi/lo bf16 [N,K]
__global__ __launch_bounds__(256) void splitT_kernel(
    const float* __restrict__ in, __nv_bfloat16* __restrict__ hi,
    __nv_bfloat16* __restrict__ lo, int K, int N)
{
    __shared__ float t[32][33];
    const int n0 = blockIdx.x << 5;
    const int k0 = blockIdx.y << 5;
    const int tx = threadIdx.x, ty = threadIdx.y;   // 32 x 8
#pragma unroll
    for (int j = 0; j < 32; j += 8)
        t[ty + j][tx] = in[(size_t)(k0 + ty + j) * N + n0 + tx];
    __syncthreads();
#pragma unroll
    for (int j = 0; j < 32; j += 8) {
        float v = t[tx][ty + j];
        __nv_bfloat16 h, l;
        split_one(v, h, l);
        size_t o = (size_t)(n0 + ty + j) * K + k0 + tx;
        hi[o] = h;
        lo[o] = l;
    }
}

// ---------------------------------------------------------------------------
// Warp-MMA bf16x3 GEMM: C[M,N] = A[M,K] @ Bt[N,K]^T
// ---------------------------------------------------------------------------
#define GSM_AH 0
#define GSM_AL 16384
#define GSM_BH 32768
#define GSM_BL 49152
#define GSM_BUF 65536
#define GEMM_SMEM (2 * GSM_BUF)

__global__ __launch_bounds__(256) void gemm_mma_kernel(
    const __nv_bfloat16* __restrict__ Ah, const __nv_bfloat16* __restrict__ Al,
    const __nv_bfloat16* __restrict__ Bh, const __nv_bfloat16* __restrict__ Bl,
    float* __restrict__ C, int M, int N, int K)
{
    extern __shared__ char smem[];
    const uint32_t sb = smem_u32(smem);
    const int tid = threadIdx.x;
    const int wid = tid >> 5;
    const int lane = tid & 31;
    const int row0 = blockIdx.y << 7;
    const int col0 = blockIdx.x << 7;
    const int wm = (wid & 1) << 6;
    const int wn = (wid >> 1) << 5;

    const int lr0 = tid >> 1;
    const int lk0 = (tid & 1) << 2;

    float acc[4][4][4];
#pragma unroll
    for (int mt = 0; mt < 4; ++mt)
#pragma unroll
        for (int nt = 0; nt < 4; ++nt)
#pragma unroll
            for (int r = 0; r < 4; ++r) acc[mt][nt][r] = 0.f;

    const int nk = K >> 6;

    auto load_tile = [&](int kb, int buf) {
        const uint32_t s0 = sb + buf * GSM_BUF;
#pragma unroll
        for (int cc = 0; cc < 4; ++cc) {
            const int r = lr0;
            const int k8 = lk0 + cc;
            const size_t offA = (size_t)(row0 + r) * K + kb + (k8 << 3);
            const size_t offB = (size_t)(col0 + r) * K + kb + (k8 << 3);
            const uint32_t so = sw128((uint32_t)((r << 7) + (k8 << 4)));
            cp16(s0 + GSM_AH + so, Ah + offA);
            cp16(s0 + GSM_AL + so, Al + offA);
            cp16(s0 + GSM_BH + so, Bh + offB);
            cp16(s0 + GSM_BL + so, Bl + offB);
        }
        cp_commit();
    };

    load_tile(0, 0);

    const int la_r = lane & 15;
    const int la_c = lane >> 4;
    const int lb_r = ((lane >> 4) << 3) + (lane & 7);
    const int lb_c = (lane >> 3) & 1;

    for (int it = 0; it < nk; ++it) {
        if (it + 1 < nk) { load_tile((it + 1) << 6, (it + 1) & 1); cp_wait<1>(); }
        else             { cp_wait<0>(); }
        __syncthreads();
        const uint32_t s0 = sb + (it & 1) * GSM_BUF;

#pragma unroll
        for (int ks = 0; ks < 4; ++ks) {
            uint32_t ah[4][4], al[4][4], bh[2][4], bl[2][4];
#pragma unroll
            for (int mt = 0; mt < 4; ++mt) {
                const uint32_t so =
                    sw128((uint32_t)(((wm + (mt << 4) + la_r) << 7) + (((ks << 1) + la_c) << 4)));
                ldm_x4(s0 + GSM_AH + so, ah[mt]);
                ldm_x4(s0 + GSM_AL + so, al[mt]);
            }
#pragma unroll
            for (int p = 0; p < 2; ++p) {
                const uint32_t so =
                    sw128((uint32_t)(((wn + (p << 4) + lb_r) << 7) + (((ks << 1) + lb_c) << 4)));
                ldm_x4(s0 + GSM_BH + so, bh[p]);
                ldm_x4(s0 + GSM_BL + so, bl[p]);
            }
#pragma unroll
            for (int mt = 0; mt < 4; ++mt)
#pragma unroll
                for (int nt = 0; nt < 4; ++nt) {
                    const uint32_t* bhp = &bh[nt >> 1][(nt & 1) << 1];
                    const uint32_t* blp = &bl[nt >> 1][(nt & 1) << 1];
                    mma16816(acc[mt][nt], ah[mt], bhp);
                    mma16816(acc[mt][nt], ah[mt], blp);
                    mma16816(acc[mt][nt], al[mt], bhp);
                }
        }
        __syncthreads();
    }

    const int g = lane >> 2, tg = lane & 3;
#pragma unroll
    for (int mt = 0; mt < 4; ++mt)
#pragma unroll
        for (int nt = 0; nt < 4; ++nt) {
            const int row = row0 + wm + (mt << 4) + g;
            const int col = col0 + wn + (nt << 3) + (tg << 1);
            *(float2*)(C + (size_t)row * N + col) = make_float2(acc[mt][nt][0], acc[mt][nt][1]);
            *(float2*)(C + (size_t)(row + 8) * N + col) = make_float2(acc[mt][nt][2], acc[mt][nt][3]);
        }
}

// ---------------------------------------------------------------------------
// Fused LayerNorm + split: qkv fp32 [b,s,3,h,d] ->
//   q: LN, *0.125, split -> qh/ql [b,h,s,d]
//   k: LN, split -> kh/kl ; v: split -> vh/vl
// One warp per (b,s,h) row; lane holds 2 elements of each of q,k,v.
// ---------------------------------------------------------------------------
__global__ __launch_bounds__(256) void ln_split_kernel(
    const float* __restrict__ qkv,
    const float* __restrict__ qs, const float* __restrict__ qbias,
    const float* __restrict__ ks, const float* __restrict__ kbias,
    __nv_bfloat16* __restrict__ qh, __nv_bfloat16* __restrict__ ql,
    __nv_bfloat16* __restrict__ kh, __nv_bfloat16* __restrict__ kl,
    __nv_bfloat16* __restrict__ vh, __nv_bfloat16* __restrict__ vl)
{
    const int w = (int)((blockIdx.x * 256u + threadIdx.x) >> 5);   // row over B*S*H
    const int lane = threadIdx.x & 31;
    const int h = w & 15;
    const int bs = w >> 4;               // b*2048 + s
    const int b = bs >> 11, s = bs & 2047;
    const float* p = qkv + (size_t)bs * 3072 + h * 64 + lane * 2;

    float2 qv = *(const float2*)p;
    float2 kv = *(const float2*)(p + 1024);
    float2 vv = *(const float2*)(p + 2048);

    float sq = qv.x + qv.y, qq = qv.x * qv.x + qv.y * qv.y;
    float sk = kv.x + kv.y, kk = kv.x * kv.x + kv.y * kv.y;
#pragma unroll
    for (int off = 16; off; off >>= 1) {
        sq += __shfl_xor_sync(0xffffffffu, sq, off);
        qq += __shfl_xor_sync(0xffffffffu, qq, off);
        sk += __shfl_xor_sync(0xffffffffu, sk, off);
        kk += __shfl_xor_sync(0xffffffffu, kk, off);
    }
    float qm = sq * (1.f / 64.f);
    float qr = rsqrtf(fmaxf(qq * (1.f / 64.f) - qm * qm, 0.f) + 1e-5f);
    float km = sk * (1.f / 64.f);
    float kr = rsqrtf(fmaxf(kk * (1.f / 64.f) - km * km, 0.f) + 1e-5f);

    float2 scq = *(const float2*)(qs + lane * 2);
    float2 biq = *(const float2*)(qbias + lane * 2);
    float2 sck = *(const float2*)(ks + lane * 2);
    float2 bik = *(const float2*)(kbias + lane * 2);

    // fold 1/sqrt(64) into q (exact power-of-two scale)
    float qnx = ((qv.x - qm) * qr * scq.x + biq.x) * 0.125f;
    float qny = ((qv.y - qm) * qr * scq.y + biq.y) * 0.125f;
    float knx = (kv.x - km) * kr * sck.x + bik.x;
    float kny = (kv.y - km) * kr * sck.y + bik.y;

    const size_t o = (((size_t)(b * TH + h)) * TS + s) * 64 + lane * 2;
    uint32_t hw, lw;
    split2(qnx, qny, hw, lw);
    *(uint32_t*)(qh + o) = hw; *(uint32_t*)(ql + o) = lw;
    split2(knx, kny, hw, lw);
    *(uint32_t*)(kh + o) = hw; *(uint32_t*)(kl + o) = lw;
    split2(vv.x, vv.y, hw, lw);
    *(uint32_t*)(vh + o) = hw; *(uint32_t*)(vl + o) = lw;
}

__global__ void zero4_kernel(float* p) { p[threadIdx.x] = 0.f; }

// ---------------------------------------------------------------------------
// Flash attention on mma.sync (bf16x3) + streaming entropy.
// CTA: 64 q-rows, 4 warps (warp = m16 x n64), 128 threads. K-tile = 64 keys.
// Operands arrive PRE-SPLIT bf16 in [b,h,s,d] layout: staging is pure cp.async
// straight into the swizzled smem layout, double-buffered (2 x 32KB).
// Q pre-scaled by 1/8 at ln_split time. Epilogue: fp32 ctx (R4-proven config).
// ---------------------------------------------------------------------------
#define AB_KH 0
#define AB_KL 8192
#define AB_VH 16384
#define AB_VL 24576
#define AB_BUF 32768
#define ATTN_SMEM 65536

__global__ __launch_bounds__(128) void attn_mma_kernel(
    const __nv_bfloat16* __restrict__ qhg, const __nv_bfloat16* __restrict__ qlg,
    const __nv_bfloat16* __restrict__ khg, const __nv_bfloat16* __restrict__ klg,
    const __nv_bfloat16* __restrict__ vhg, const __nv_bfloat16* __restrict__ vlg,
    float* __restrict__ ctx, float* __restrict__ ent)
{
    extern __shared__ char smA[];
    __shared__ float red[4];
    const uint32_t sb = smem_u32(smA);

    const int tid = threadIdx.x, wid = tid >> 5, lane = tid & 31;
    const int qb0 = blockIdx.x << 6;           // 64 q rows per CTA
    const int h = blockIdx.y, b = blockIdx.z;
    const size_t bh = ((size_t)(b * TH + h)) * TS * 64;

    // ---- prologue: Q -> buf1 (group 0) ----
#pragma unroll
    for (int j = 0; j < 4; ++j) {
        int c = tid + 128 * j;                 // 512 chunks per array
        int row = c >> 3, k8 = c & 7;
        size_t g = bh + (size_t)(qb0 + row) * 64 + (k8 << 3);
        uint32_t so = sw128((uint32_t)((row << 7) + (k8 << 4)));
        cp16(sb + AB_BUF + AB_KH + so, qhg + g);
        cp16(sb + AB_BUF + AB_KL + so, qlg + g);
    }
    cp_commit();

    auto load_kv = [&](int kt) {
        const uint32_t bufb = sb + (uint32_t)(kt & 1) * AB_BUF;
#pragma unroll
        for (int j = 0; j < 4; ++j) {
            int c = tid + 128 * j;
            int row = c >> 3, k8 = c & 7;
            size_t g = bh + (size_t)((kt << 6) + row) * 64 + (k8 << 3);
            uint32_t so = sw128((uint32_t)((row << 7) + (k8 << 4)));
            cp16(bufb + AB_KH + so, khg + g);
            cp16(bufb + AB_KL + so, klg + g);
            cp16(bufb + AB_VH + so, vhg + g);
            cp16(bufb + AB_VL + so, vlg + g);
        }
        cp_commit();
    };
    load_kv(0);                                // tile 0 -> buf0 (group 1)

    cp_wait<1>();                              // Q group retired (FIFO order)
    __syncthreads();

    // ---- extract Q A-fragments (hi/lo) from buf1 ----
    uint32_t qh[4][4], ql[4][4];
    {
        const int row = (wid << 4) + (lane & 15);
        const int cb = (lane >> 4) << 4;
#pragma unroll
        for (int s = 0; s < 4; ++s) {
            uint32_t so = sw128((uint32_t)(row * 128 + s * 32 + cb));
            ldm_x4(sb + AB_BUF + AB_KH + so, qh[s]);
            ldm_x4(sb + AB_BUF + AB_KL + so, ql[s]);
        }
    }
    __syncthreads();                           // buf1 free for tile 1

    float o[8][4];
#pragma unroll
    for (int nt = 0; nt < 8; ++nt)
#pragma unroll
        for (int r = 0; r < 4; ++r) o[nt][r] = 0.f;
    float m2[2] = {-1e30f, -1e30f}, l2[2] = {0.f, 0.f}, T2[2] = {0.f, 0.f};

    const int kb_row = ((lane >> 4) << 3) + (lane & 7);
    const int kb_c = (lane >> 3) & 1;
    const int v_key = (((lane >> 3) & 1) << 3) + (lane & 7);
    const int v_d = (lane >> 4) << 3;

    for (int kt = 0; kt < TS / 64; ++kt) {
        if (kt + 1 < TS / 64) { load_kv(kt + 1); cp_wait<1>(); }
        else                  { cp_wait<0>(); }
        __syncthreads();
        const uint32_t bufb = sb + (uint32_t)(kt & 1) * AB_BUF;

        // ---- S = Q K^T (bf16x3) ----
        float s4[8][4];
#pragma unroll
        for (int nt = 0; nt < 8; ++nt)
#pragma unroll
            for (int r = 0; r < 4; ++r) s4[nt][r] = 0.f;

#pragma unroll
        for (int s = 0; s < 4; ++s) {
            uint32_t kbh[4][4], kbl[4][4];
#pragma unroll
            for (int p = 0; p < 4; ++p) {
                uint32_t so = sw128((uint32_t)(((p << 4) + kb_row) * 128 + s * 32 + kb_c * 16));
                ldm_x4(bufb + AB_KH + so, kbh[p]);
                ldm_x4(bufb + AB_KL + so, kbl[p]);
            }
#pragma unroll
            for (int nt = 0; nt < 8; ++nt) {
                const uint32_t* bh2 = &kbh[nt >> 1][(nt & 1) << 1];
                const uint32_t* bl2 = &kbl[nt >> 1][(nt & 1) << 1];
                mma16816(s4[nt], qh[s], bh2);
                mma16816(s4[nt], qh[s], bl2);
                mma16816(s4[nt], ql[s], bh2);
            }
        }

        // ---- online softmax + entropy terms (rows g, g+8 per thread) ----
        float mx0 = s4[0][0], mx1 = s4[0][2];
#pragma unroll
        for (int nt = 0; nt < 8; ++nt) {
            mx0 = fmaxf(mx0, fmaxf(s4[nt][0], s4[nt][1]));
            mx1 = fmaxf(mx1, fmaxf(s4[nt][2], s4[nt][3]));
        }
#pragma unroll
        for (int off = 1; off <= 2; off <<= 1) {
            mx0 = fmaxf(mx0, __shfl_xor_sync(0xffffffffu, mx0, off));
            mx1 = fmaxf(mx1, __shfl_xor_sync(0xffffffffu, mx1, off));
        }
        float mn0 = fmaxf(m2[0], mx0), mn1 = fmaxf(m2[1], mx1);
        float ls0 = 0.f, ts0 = 0.f, ls1 = 0.f, ts1 = 0.f;
#pragma unroll
        for (int nt = 0; nt < 8; ++nt) {
            float d0 = s4[nt][0] - mn0, d1 = s4[nt][1] - mn0;
            float d2 = s4[nt][2] - mn1, d3 = s4[nt][3] - mn1;
            float e0 = __expf(d0), e1 = __expf(d1), e2 = __expf(d2), e3 = __expf(d3);
            s4[nt][0] = e0; s4[nt][1] = e1; s4[nt][2] = e2; s4[nt][3] = e3;
            ls0 += e0 + e1; ls1 += e2 + e3;
            ts0 = fmaf(e0, d0, fmaf(e1, d1, ts0));
            ts1 = fmaf(e2, d2, fmaf(e3, d3, ts1));
        }
#pragma unroll
        for (int off = 1; off <= 2; off <<= 1) {
            ls0 += __shfl_xor_sync(0xffffffffu, ls0, off);
            ts0 += __shfl_xor_sync(0xffffffffu, ts0, off);
            ls1 += __shfl_xor_sync(0xffffffffu, ls1, off);
            ts1 += __shfl_xor_sync(0xffffffffu, ts1, off);
        }
        float dm0 = mn0 - m2[0], c0 = __expf(-dm0);
        float dm1 = mn1 - m2[1], c1 = __expf(-dm1);
        T2[0] = fmaf(c0, T2[0] - dm0 * l2[0], ts0);
        T2[1] = fmaf(c1, T2[1] - dm1 * l2[1], ts1);
        l2[0] = fmaf(l2[0], c0, ls0);
        l2[1] = fmaf(l2[1], c1, ls1);
        m2[0] = mn0; m2[1] = mn1;
#pragma unroll
        for (int nt = 0; nt < 8; ++nt) {
            o[nt][0] *= c0; o[nt][1] *= c0;
            o[nt][2] *= c1; o[nt][3] *= c1;
        }

        // ---- O += P V (bf16x3; P from frags, V via ldmatrix.trans) ----
#pragma unroll
        for (int s = 0; s < 4; ++s) {
            uint32_t pah[4], pal[4];
            split2(s4[2 * s][0],     s4[2 * s][1],     pah[0], pal[0]);
            split2(s4[2 * s][2],     s4[2 * s][3],     pah[1], pal[1]);
            split2(s4[2 * s + 1][0], s4[2 * s + 1][1], pah[2], pal[2]);
            split2(s4[2 * s + 1][2], s4[2 * s + 1][3], pah[3], pal[3]);
            uint32_t vbh[4][4], vbl[4][4];
#pragma unroll
            for (int p2 = 0; p2 < 4; ++p2) {
                uint32_t so = sw128((uint32_t)(((s << 4) + v_key) * 128 + ((p2 << 4) + v_d) * 2));
                ldm_x4_t(bufb + AB_VH + so, vbh[p2]);
                ldm_x4_t(bufb + AB_VL + so, vbl[p2]);
            }
#pragma unroll
            for (int nt = 0; nt < 8; ++nt) {
                const uint32_t* bh2 = &vbh[nt >> 1][(nt & 1) << 1];
                const uint32_t* bl2 = &vbl[nt >> 1][(nt & 1) << 1];
                mma16816(o[nt], pah, bh2);
                mma16816(o[nt], pah, bl2);
                mma16816(o[nt], pal, bh2);
            }
        }
        __syncthreads();   // all warps done reading buf before next overwrite
    }

    // ---- write context fp32 (R4-proven epilogue) ----
    {
        float rl0 = 1.f / l2[0], rl1 = 1.f / l2[1];
        const int r0 = qb0 + (wid << 4) + (lane >> 2);
        const int cb = (h << 6) + ((lane & 3) << 1);
#pragma unroll
        for (int nt = 0; nt < 8; ++nt) {
            const int col = cb + (nt << 3);
            *(float2*)(ctx + (size_t)(b * TS + r0) * 1024 + col) =
                make_float2(o[nt][0] * rl0, o[nt][1] * rl0);
            *(float2*)(ctx + (size_t)(b * TS + r0 + 8) * 1024 + col) =
                make_float2(o[nt][2] * rl1, o[nt][3] * rl1);
        }
    }

    // ---- entropy: per-row log(l) - T/l, reduce, one atomic per CTA ----
    float e = 0.f;
    if ((lane & 3) == 0)
        e = (__logf(l2[0]) - T2[0] / l2[0]) + (__logf(l2[1]) - T2[1] / l2[1]);
#pragma unroll
    for (int off = 16; off; off >>= 1) e += __shfl_xor_sync(0xffffffffu, e, off);
    if (lane == 0) red[wid] = e;
    __syncthreads();
    if (tid == 0) {
        float esum = red[0] + red[1] + red[2] + red[3];
        const float ent_scale = (float)(1.0 / (7.6246189861593985 * (double)(TH * TS)));
        atomicAdd(ent + b, esum * ent_scale);
    }
}

// ---------------------------------------------------------------------------
extern "C" void kernel_launch(void* const* d_in, const int* in_sizes, int n_in,
                              void* d_out, int out_size)
{
    const float* x       = (const float*)d_in[0];
    const float* w_qkv   = (const float*)d_in[1];
    const float* w_proj  = (const float*)d_in[2];
    const float* q_scale = (const float*)d_in[3];
    const float* q_bias  = (const float*)d_in[4];
    const float* k_scale = (const float*)d_in[5];
    const float* k_bias  = (const float*)d_in[6];
    float* out = (float*)d_out;

    float *qkv, *ctx, *entpad;
    cudaGetSymbolAddress((void**)&qkv, g_qkv);
    cudaGetSymbolAddress((void**)&ctx, g_ctx);
    cudaGetSymbolAddress((void**)&entpad, g_entpad);
    __nv_bfloat16 *xh, *xl, *wqh, *wql, *ch, *cl, *wph, *wpl;
    __nv_bfloat16 *qh2, *ql2, *kh2, *kl2, *vh2, *vl2;
    cudaGetSymbolAddress((void**)&xh, g_xh);
    cudaGetSymbolAddress((void**)&xl, g_xl);
    cudaGetSymbolAddress((void**)&wqh, g_wqh);
    cudaGetSymbolAddress((void**)&wql, g_wql);
    cudaGetSymbolAddress((void**)&ch, g_ch);
    cudaGetSymbolAddress((void**)&cl, g_cl);
    cudaGetSymbolAddress((void**)&wph, g_wph);
    cudaGetSymbolAddress((void**)&wpl, g_wpl);
    cudaGetSymbolAddress((void**)&qh2, g_qh2);
    cudaGetSymbolAddress((void**)&ql2, g_ql2);
    cudaGetSymbolAddress((void**)&kh2, g_kh2);
    cudaGetSymbolAddress((void**)&kl2, g_kl2);
    cudaGetSymbolAddress((void**)&vh2, g_vh2);
    cudaGetSymbolAddress((void**)&vl2, g_vl2);

    cudaFuncSetAttribute(gemm_mma_kernel, cudaFuncAttributeMaxDynamicSharedMemorySize, GEMM_SMEM);
    cudaFuncSetAttribute(attn_mma_kernel, cudaFuncAttributeMaxDynamicSharedMemorySize, ATTN_SMEM);

    const int BS = TB * TS;                 // 8192
    const size_t main_elems = (size_t)BS * TC;
    float* ent = (out_size >= (int)(main_elems + TB)) ? (out + main_elems) : entpad;

    // 1) split x -> bf16 hi/lo ; transpose+split w_qkv
    {
        int n4 = (BS * TC) / 4;
        split_kernel<<<(n4 + 255) / 256, 256>>>((const float4*)x, xh, xl, n4);
        splitT_kernel<<<dim3(3 * TC / 32, TC / 32), dim3(32, 8)>>>(w_qkv, wqh, wql, TC, 3 * TC);
    }

    // 2) QKV projection on tensor cores (mma.sync): [8192,1024] @ [1024,3072]
    gemm_mma_kernel<<<dim3(3 * TC / 128, BS / 128), 256, GEMM_SMEM>>>(
        xh, xl, wqh, wql, qkv, BS, 3 * TC, TC);

    // 3) fused LayerNorm + split -> pre-split bf16 q/k/v in [b,h,s,d]
    ln_split_kernel<<<(TB * TS * TH) / 8, 256>>>(
        qkv, q_scale, q_bias, k_scale, k_bias, qh2, ql2, kh2, kl2, vh2, vl2);

    // 4) zero entropy accumulators
    zero4_kernel<<<1, TB>>>(ent);

    // 5) fused attention + entropy -> ctx fp32 (cp.async double-buffered)
    attn_mma_kernel<<<dim3(TS / 64, TH, TB), 128, ATTN_SMEM>>>(
        qh2, ql2, kh2, kl2, vh2, vl2, ctx, ent);

    // 6) split ctx ; transpose+split w_proj
    {
        int n4 = (BS * TC) / 4;
        split_kernel<<<(n4 + 255) / 256, 256>>>((const float4*)ctx, ch, cl, n4);
        splitT_kernel<<<dim3(TC / 32, TC / 32), dim3(32, 8)>>>(w_proj, wph, wpl, TC, TC);
    }

    // 7) output projection on tensor cores: [8192,1024] @ [1024,1024]
    gemm_mma_kernel<<<dim3(TC / 128, BS / 128), 256, GEMM_SMEM>>>(
        ch, cl, wph, wpl, out, BS, TC, TC);
}

// round 8
// speedup vs baseline: 1.4732x; 1.3476x over previous
#include <cuda_runtime.h>
#include <cuda_fp16.h>
#include <cstdint>

#define TB 4
#define TS 2048
#define TH 16
#define TD 64
#define TC 1024

// ---------------------------------------------------------------------------
// Scratch (alloc-free rule: __device__ globals)
// ---------------------------------------------------------------------------
static __device__ float g_qkv[(size_t)8192 * 3072];          // [B*S, 3*C] fp32
static __device__ float g_ctx[(size_t)8192 * 1024];          // [B*S, C]   fp32
static __device__ float g_entpad[4];
// fp16 split operands (GEMM): activations hi/lo, weights single
static __device__ __half g_xh[(size_t)8192 * 1024];
static __device__ __half g_xl[(size_t)8192 * 1024];
static __device__ __half g_wq[(size_t)3072 * 1024];          // w_qkv^T [N,K] single
static __device__ __half g_ch[(size_t)8192 * 1024];
static __device__ __half g_cl[(size_t)8192 * 1024];
static __device__ __half g_wp[(size_t)1024 * 1024];          // w_proj^T [N,K] single
// pre-split attention operands, [b,h,s,d] layout (contiguous 64-elem rows)
#define NBH ((size_t)TB * TH * TS * 64)
static __device__ __half g_qh2[NBH];
static __device__ __half g_ql2[NBH];
static __device__ __half g_kh2[NBH];                          // K single fp16
static __device__ __half g_vh2[NBH];
static __device__ __half g_vl2[NBH];

// ---------------------------------------------------------------------------
// Helpers (sm_103 base target: ldmatrix + mma.sync + cp.async only)
// ---------------------------------------------------------------------------
__device__ __forceinline__ uint32_t smem_u32(const void* p) {
    uint32_t a;
    asm("{ .reg .u64 t; cvta.to.shared.u64 t, %1; cvt.u32.u64 %0, t; }" : "=r"(a) : "l"(p));
    return a;
}
__device__ __forceinline__ uint32_t sw128(uint32_t off) { return off ^ ((off >> 3) & 0x70); }

__device__ __forceinline__ void cp16(uint32_t saddr, const void* gptr) {
    asm volatile("cp.async.cg.shared.global [%0], [%1], 16;" :: "r"(saddr), "l"(gptr));
}
__device__ __forceinline__ void cp_commit() {
    asm volatile("cp.async.commit_group;" ::: "memory");
}
template <int N>
__device__ __forceinline__ void cp_wait() {
    asm volatile("cp.async.wait_group %0;" :: "n"(N) : "memory");
}

__device__ __forceinline__ void ldm_x4(uint32_t addr, uint32_t r[4]) {
    asm volatile("ldmatrix.sync.aligned.m8n8.x4.shared.b16 {%0,%1,%2,%3}, [%4];"
                 : "=r"(r[0]), "=r"(r[1]), "=r"(r[2]), "=r"(r[3]) : "r"(addr));
}
__device__ __forceinline__ void ldm_x4_t(uint32_t addr, uint32_t r[4]) {
    asm volatile("ldmatrix.sync.aligned.m8n8.x4.trans.shared.b16 {%0,%1,%2,%3}, [%4];"
                 : "=r"(r[0]), "=r"(r[1]), "=r"(r[2]), "=r"(r[3]) : "r"(addr));
}

__device__ __forceinline__ void mma16816(float d[4], const uint32_t a[4], const uint32_t b[2]) {
    asm volatile(
        "mma.sync.aligned.m16n8k16.row.col.f32.f16.f16.f32 "
        "{%0,%1,%2,%3}, {%4,%5,%6,%7}, {%8,%9}, {%0,%1,%2,%3};"
        : "+f"(d[0]), "+f"(d[1]), "+f"(d[2]), "+f"(d[3])
        : "r"(a[0]), "r"(a[1]), "r"(a[2]), "r"(a[3]), "r"(b[0]), "r"(b[1]));
}

// pack two floats into fp16x2 (a = low, b = high)
__device__ __forceinline__ uint32_t cvt2h(float a, float b) {
    __half2 h = __floats2half2_rn(a, b);
    return *(uint32_t*)&h;
}
// split two floats into packed fp16x2 hi + lo halves
__device__ __forceinline__ void split2h(float a, float b, uint32_t& hi, uint32_t& lo) {
    __half2 h = __floats2half2_rn(a, b);
    float ra = a - __low2float(h);
    float rb = b - __high2float(h);
    __half2 l = __floats2half2_rn(ra, rb);
    hi = *(uint32_t*)&h;
    lo = *(uint32_t*)&l;
}

// ---------------------------------------------------------------------------
// Conversion kernels
// ---------------------------------------------------------------------------
__global__ __launch_bounds__(256) void split_kernel(
    const float4* __restrict__ in, __half* __restrict__ hi,
    __half* __restrict__ lo, int n4)
{
    int i = blockIdx.x * 256 + threadIdx.x;
    if (i >= n4) return;
    float4 v = in[i];
    uint32_t h01, h23, l01, l23;
    split2h(v.x, v.y, h01, l01);
    split2h(v.z, v.w, h23, l23);
    ((uint2*)hi)[i] = make_uint2(h01, h23);
    ((uint2*)lo)[i] = make_uint2(l01, l23);
}

// Transpose + single fp16: in f32 [K,N] -> hi fp16 [N,K]
__global__ __launch_bounds__(256) void splitTs_kernel(
    const float* __restrict__ in, __half* __restrict__ hi, int K, int N)
{
    __shared__ float t[32][33];
    const int n0 = blockIdx.x << 5;
    const int k0 = blockIdx.y << 5;
    const int tx = threadIdx.x, ty = threadIdx.y;   // 32 x 8
#pragma unroll
    for (int j = 0; j < 32; j += 8)
        t[ty + j][tx] = in[(size_t)(k0 + ty + j) * N + n0 + tx];
    __syncthreads();
#pragma unroll
    for (int j = 0; j < 32; j += 8) {
        size_t o = (size_t)(n0 + ty + j) * K + k0 + tx;
        hi[o] = __float2half_rn(t[tx][ty + j]);
    }
}

// ---------------------------------------------------------------------------
// Warp-MMA fp16x2 GEMM: C[M,N] = (Ah+Al)[M,K] @ B[N,K]^T  (B single fp16)
// CTA 128x128, K-tile 64, 8 warps; smem 3 arrays/stage (48KB), 2 stages.
// ---------------------------------------------------------------------------
#define GSM_AH 0
#define GSM_AL 16384
#define GSM_B  32768
#define GSM_BUF 49152
#define GEMM_SMEM (2 * GSM_BUF)

__global__ __launch_bounds__(256) void gemm_mma_kernel(
    const __half* __restrict__ Ah, const __half* __restrict__ Al,
    const __half* __restrict__ B, float* __restrict__ C, int M, int N, int K)
{
    extern __shared__ char smem[];
    const uint32_t sb = smem_u32(smem);
    const int tid = threadIdx.x;
    const int wid = tid >> 5;
    const int lane = tid & 31;
    const int row0 = blockIdx.y << 7;
    const int col0 = blockIdx.x << 7;
    const int wm = (wid & 1) << 6;
    const int wn = (wid >> 1) << 5;

    const int lr0 = tid >> 1;
    const int lk0 = (tid & 1) << 2;

    float acc[4][4][4];
#pragma unroll
    for (int mt = 0; mt < 4; ++mt)
#pragma unroll
        for (int nt = 0; nt < 4; ++nt)
#pragma unroll
            for (int r = 0; r < 4; ++r) acc[mt][nt][r] = 0.f;

    const int nk = K >> 6;

    auto load_tile = [&](int kb, int buf) {
        const uint32_t s0 = sb + buf * GSM_BUF;
#pragma unroll
        for (int cc = 0; cc < 4; ++cc) {
            const int r = lr0;
            const int k8 = lk0 + cc;
            const size_t offA = (size_t)(row0 + r) * K + kb + (k8 << 3);
            const size_t offB = (size_t)(col0 + r) * K + kb + (k8 << 3);
            const uint32_t so = sw128((uint32_t)((r << 7) + (k8 << 4)));
            cp16(s0 + GSM_AH + so, Ah + offA);
            cp16(s0 + GSM_AL + so, Al + offA);
            cp16(s0 + GSM_B + so, B + offB);
        }
        cp_commit();
    };

    load_tile(0, 0);

    const int la_r = lane & 15;
    const int la_c = lane >> 4;
    const int lb_r = ((lane >> 4) << 3) + (lane & 7);
    const int lb_c = (lane >> 3) & 1;

    for (int it = 0; it < nk; ++it) {
        if (it + 1 < nk) { load_tile((it + 1) << 6, (it + 1) & 1); cp_wait<1>(); }
        else             { cp_wait<0>(); }
        __syncthreads();
        const uint32_t s0 = sb + (it & 1) * GSM_BUF;

#pragma unroll
        for (int ks = 0; ks < 4; ++ks) {
            uint32_t ah[4][4], al[4][4], bh[2][4];
#pragma unroll
            for (int mt = 0; mt < 4; ++mt) {
                const uint32_t so =
                    sw128((uint32_t)(((wm + (mt << 4) + la_r) << 7) + (((ks << 1) + la_c) << 4)));
                ldm_x4(s0 + GSM_AH + so, ah[mt]);
                ldm_x4(s0 + GSM_AL + so, al[mt]);
            }
#pragma unroll
            for (int p = 0; p < 2; ++p) {
                const uint32_t so =
                    sw128((uint32_t)(((wn + (p << 4) + lb_r) << 7) + (((ks << 1) + lb_c) << 4)));
                ldm_x4(s0 + GSM_B + so, bh[p]);
            }
#pragma unroll
            for (int mt = 0; mt < 4; ++mt)
#pragma unroll
                for (int nt = 0; nt < 4; ++nt) {
                    const uint32_t* bp = &bh[nt >> 1][(nt & 1) << 1];
                    mma16816(acc[mt][nt], ah[mt], bp);
                    mma16816(acc[mt][nt], al[mt], bp);
                }
        }
        __syncthreads();
    }

    const int g = lane >> 2, tg = lane & 3;
#pragma unroll
    for (int mt = 0; mt < 4; ++mt)
#pragma unroll
        for (int nt = 0; nt < 4; ++nt) {
            const int row = row0 + wm + (mt << 4) + g;
            const int col = col0 + wn + (nt << 3) + (tg << 1);
            *(float2*)(C + (size_t)row * N + col) = make_float2(acc[mt][nt][0], acc[mt][nt][1]);
            *(float2*)(C + (size_t)(row + 8) * N + col) = make_float2(acc[mt][nt][2], acc[mt][nt][3]);
        }
}

// ---------------------------------------------------------------------------
// Fused LayerNorm + split: qkv fp32 [b,s,3,h,d] ->
//   q: LN, *0.125, fp16 split -> qh/ql [b,h,s,d]
//   k: LN, SINGLE fp16 -> kh ; v: fp16 split -> vh/vl
// ---------------------------------------------------------------------------
__global__ __launch_bounds__(256) void ln_split_kernel(
    const float* __restrict__ qkv,
    const float* __restrict__ qs, const float* __restrict__ qbias,
    const float* __restrict__ ks, const float* __restrict__ kbias,
    __half* __restrict__ qh, __half* __restrict__ ql,
    __half* __restrict__ kh,
    __half* __restrict__ vh, __half* __restrict__ vl)
{
    const int w = (int)((blockIdx.x * 256u + threadIdx.x) >> 5);   // row over B*S*H
    const int lane = threadIdx.x & 31;
    const int h = w & 15;
    const int bs = w >> 4;
    const int b = bs >> 11, s = bs & 2047;
    const float* p = qkv + (size_t)bs * 3072 + h * 64 + lane * 2;

    float2 qv = *(const float2*)p;
    float2 kv = *(const float2*)(p + 1024);
    float2 vv = *(const float2*)(p + 2048);

    float sq = qv.x + qv.y, qq = qv.x * qv.x + qv.y * qv.y;
    float sk = kv.x + kv.y, kk = kv.x * kv.x + kv.y * kv.y;
#pragma unroll
    for (int off = 16; off; off >>= 1) {
        sq += __shfl_xor_sync(0xffffffffu, sq, off);
        qq += __shfl_xor_sync(0xffffffffu, qq, off);
        sk += __shfl_xor_sync(0xffffffffu, sk, off);
        kk += __shfl_xor_sync(0xffffffffu, kk, off);
    }
    float qm = sq * (1.f / 64.f);
    float qr = rsqrtf(fmaxf(qq * (1.f / 64.f) - qm * qm, 0.f) + 1e-5f);
    float km = sk * (1.f / 64.f);
    float kr = rsqrtf(fmaxf(kk * (1.f / 64.f) - km * km, 0.f) + 1e-5f);

    float2 scq = *(const float2*)(qs + lane * 2);
    float2 biq = *(const float2*)(qbias + lane * 2);
    float2 sck = *(const float2*)(ks + lane * 2);
    float2 bik = *(const float2*)(kbias + lane * 2);

    float qnx = ((qv.x - qm) * qr * scq.x + biq.x) * 0.125f;
    float qny = ((qv.y - qm) * qr * scq.y + biq.y) * 0.125f;
    float knx = (kv.x - km) * kr * sck.x + bik.x;
    float kny = (kv.y - km) * kr * sck.y + bik.y;

    const size_t o = (((size_t)(b * TH + h)) * TS + s) * 64 + lane * 2;
    uint32_t hw, lw;
    split2h(qnx, qny, hw, lw);
    *(uint32_t*)(qh + o) = hw; *(uint32_t*)(ql + o) = lw;
    *(uint32_t*)(kh + o) = cvt2h(knx, kny);
    split2h(vv.x, vv.y, hw, lw);
    *(uint32_t*)(vh + o) = hw; *(uint32_t*)(vl + o) = lw;
}

__global__ void zero4_kernel(float* p) { p[threadIdx.x] = 0.f; }

// ---------------------------------------------------------------------------
// Flash attention on mma.sync (fp16x2) + streaming entropy.
// CTA: 64 q-rows, 4 warps (warp = m16 x n64), 128 threads. K-tile = 64 keys.
// S = (Qh+Ql)·K (K single fp16) ; O += P(single fp16)·(Vh+Vl).
// Smem: double-buffered {K, VH, VL} (24KB each) + persistent Q hi/lo (16KB).
// ---------------------------------------------------------------------------
#define AB_K  0
#define AB_VH 8192
#define AB_VL 16384
#define AB_BUF 24576
#define AQ_H 49152
#define AQ_L 57344
#define ATTN_SMEM 65536

__global__ __launch_bounds__(128) void attn_mma_kernel(
    const __half* __restrict__ qhg, const __half* __restrict__ qlg,
    const __half* __restrict__ khg,
    const __half* __restrict__ vhg, const __half* __restrict__ vlg,
    float* __restrict__ ctx, float* __restrict__ ent)
{
    extern __shared__ char smA[];
    __shared__ float red[4];
    const uint32_t sb = smem_u32(smA);

    const int tid = threadIdx.x, wid = tid >> 5, lane = tid & 31;
    const int qb0 = blockIdx.x << 6;           // 64 q rows per CTA
    const int h = blockIdx.y, b = blockIdx.z;
    const size_t bh = ((size_t)(b * TH + h)) * TS * 64;

    // ---- prologue: Q -> persistent region (group 0) ----
#pragma unroll
    for (int j = 0; j < 4; ++j) {
        int c = tid + 128 * j;                 // 512 chunks per array
        int row = c >> 3, k8 = c & 7;
        size_t g = bh + (size_t)(qb0 + row) * 64 + (k8 << 3);
        uint32_t so = sw128((uint32_t)((row << 7) + (k8 << 4)));
        cp16(sb + AQ_H + so, qhg + g);
        cp16(sb + AQ_L + so, qlg + g);
    }
    cp_commit();

    auto load_kv = [&](int kt) {
        const uint32_t bufb = sb + (uint32_t)(kt & 1) * AB_BUF;
#pragma unroll
        for (int j = 0; j < 4; ++j) {
            int c = tid + 128 * j;
            int row = c >> 3, k8 = c & 7;
            size_t g = bh + (size_t)((kt << 6) + row) * 64 + (k8 << 3);
            uint32_t so = sw128((uint32_t)((row << 7) + (k8 << 4)));
            cp16(bufb + AB_K + so, khg + g);
            cp16(bufb + AB_VH + so, vhg + g);
            cp16(bufb + AB_VL + so, vlg + g);
        }
        cp_commit();
    };
    load_kv(0);                                // tile 0 (group 1)

    cp_wait<1>();                              // Q group retired
    __syncthreads();

    // ---- extract Q A-fragments (hi/lo) ----
    uint32_t qh[4][4], ql[4][4];
    {
        const int row = (wid << 4) + (lane & 15);
        const int cb = (lane >> 4) << 4;
#pragma unroll
        for (int s = 0; s < 4; ++s) {
            uint32_t so = sw128((uint32_t)(row * 128 + s * 32 + cb));
            ldm_x4(sb + AQ_H + so, qh[s]);
            ldm_x4(sb + AQ_L + so, ql[s]);
        }
    }

    float o[8][4];
#pragma unroll
    for (int nt = 0; nt < 8; ++nt)
#pragma unroll
        for (int r = 0; r < 4; ++r) o[nt][r] = 0.f;
    float m2[2] = {-1e30f, -1e30f}, l2[2] = {0.f, 0.f}, T2[2] = {0.f, 0.f};

    const int kb_row = ((lane >> 4) << 3) + (lane & 7);
    const int kb_c = (lane >> 3) & 1;
    const int v_key = (((lane >> 3) & 1) << 3) + (lane & 7);
    const int v_d = (lane >> 4) << 3;

    for (int kt = 0; kt < TS / 64; ++kt) {
        if (kt + 1 < TS / 64) { load_kv(kt + 1); cp_wait<1>(); }
        else                  { cp_wait<0>(); }
        __syncthreads();
        const uint32_t bufb = sb + (uint32_t)(kt & 1) * AB_BUF;

        // ---- S = Q K^T (fp16x2: K single) ----
        float s4[8][4];
#pragma unroll
        for (int nt = 0; nt < 8; ++nt)
#pragma unroll
            for (int r = 0; r < 4; ++r) s4[nt][r] = 0.f;

#pragma unroll
        for (int s = 0; s < 4; ++s) {
            uint32_t kb[4][4];
#pragma unroll
            for (int p = 0; p < 4; ++p) {
                uint32_t so = sw128((uint32_t)(((p << 4) + kb_row) * 128 + s * 32 + kb_c * 16));
                ldm_x4(bufb + AB_K + so, kb[p]);
            }
#pragma unroll
            for (int nt = 0; nt < 8; ++nt) {
                const uint32_t* kb2 = &kb[nt >> 1][(nt & 1) << 1];
                mma16816(s4[nt], qh[s], kb2);
                mma16816(s4[nt], ql[s], kb2);
            }
        }

        // ---- online softmax + entropy terms (rows g, g+8 per thread) ----
        float mx0 = s4[0][0], mx1 = s4[0][2];
#pragma unroll
        for (int nt = 0; nt < 8; ++nt) {
            mx0 = fmaxf(mx0, fmaxf(s4[nt][0], s4[nt][1]));
            mx1 = fmaxf(mx1, fmaxf(s4[nt][2], s4[nt][3]));
        }
#pragma unroll
        for (int off = 1; off <= 2; off <<= 1) {
            mx0 = fmaxf(mx0, __shfl_xor_sync(0xffffffffu, mx0, off));
            mx1 = fmaxf(mx1, __shfl_xor_sync(0xffffffffu, mx1, off));
        }
        float mn0 = fmaxf(m2[0], mx0), mn1 = fmaxf(m2[1], mx1);
        float ls0 = 0.f, ts0 = 0.f, ls1 = 0.f, ts1 = 0.f;
#pragma unroll
        for (int nt = 0; nt < 8; ++nt) {
            float d0 = s4[nt][0] - mn0, d1 = s4[nt][1] - mn0;
            float d2 = s4[nt][2] - mn1, d3 = s4[nt][3] - mn1;
            float e0 = __expf(d0), e1 = __expf(d1), e2 = __expf(d2), e3 = __expf(d3);
            s4[nt][0] = e0; s4[nt][1] = e1; s4[nt][2] = e2; s4[nt][3] = e3;
            ls0 += e0 + e1; ls1 += e2 + e3;
            ts0 = fmaf(e0, d0, fmaf(e1, d1, ts0));
            ts1 = fmaf(e2, d2, fmaf(e3, d3, ts1));
        }
#pragma unroll
        for (int off = 1; off <= 2; off <<= 1) {
            ls0 += __shfl_xor_sync(0xffffffffu, ls0, off);
            ts0 += __shfl_xor_sync(0xffffffffu, ts0, off);
            ls1 += __shfl_xor_sync(0xffffffffu, ls1, off);
            ts1 += __shfl_xor_sync(0xffffffffu, ts1, off);
        }
        float dm0 = mn0 - m2[0], c0 = __expf(-dm0);
        float dm1 = mn1 - m2[1], c1 = __expf(-dm1);
        T2[0] = fmaf(c0, T2[0] - dm0 * l2[0], ts0);
        T2[1] = fmaf(c1, T2[1] - dm1 * l2[1], ts1);
        l2[0] = fmaf(l2[0], c0, ls0);
        l2[1] = fmaf(l2[1], c1, ls1);
        m2[0] = mn0; m2[1] = mn1;
#pragma unroll
        for (int nt = 0; nt < 8; ++nt) {
            o[nt][0] *= c0; o[nt][1] *= c0;
            o[nt][2] *= c1; o[nt][3] *= c1;
        }

        // ---- O += P V (P single fp16; V hi/lo via ldmatrix.trans) ----
#pragma unroll
        for (int s = 0; s < 4; ++s) {
            uint32_t pa[4];
            pa[0] = cvt2h(s4[2 * s][0],     s4[2 * s][1]);
            pa[1] = cvt2h(s4[2 * s][2],     s4[2 * s][3]);
            pa[2] = cvt2h(s4[2 * s + 1][0], s4[2 * s + 1][1]);
            pa[3] = cvt2h(s4[2 * s + 1][2], s4[2 * s + 1][3]);
            uint32_t vbh[4][4], vbl[4][4];
#pragma unroll
            for (int p2 = 0; p2 < 4; ++p2) {
                uint32_t so = sw128((uint32_t)(((s << 4) + v_key) * 128 + ((p2 << 4) + v_d) * 2));
                ldm_x4_t(bufb + AB_VH + so, vbh[p2]);
                ldm_x4_t(bufb + AB_VL + so, vbl[p2]);
            }
#pragma unroll
            for (int nt = 0; nt < 8; ++nt) {
                mma16816(o[nt], pa, &vbh[nt >> 1][(nt & 1) << 1]);
                mma16816(o[nt], pa, &vbl[nt >> 1][(nt & 1) << 1]);
            }
        }
        __syncthreads();   // all warps done reading buf before next overwrite
    }

    // ---- write context fp32 ----
    {
        float rl0 = 1.f / l2[0], rl1 = 1.f / l2[1];
        const int r0 = qb0 + (wid << 4) + (lane >> 2);
        const int cb = (h << 6) + ((lane & 3) << 1);
#pragma unroll
        for (int nt = 0; nt < 8; ++nt) {
            const int col = cb + (nt << 3);
            *(float2*)(ctx + (size_t)(b * TS + r0) * 1024 + col) =
                make_float2(o[nt][0] * rl0, o[nt][1] * rl0);
            *(float2*)(ctx + (size_t)(b * TS + r0 + 8) * 1024 + col) =
                make_float2(o[nt][2] * rl1, o[nt][3] * rl1);
        }
    }

    // ---- entropy: per-row log(l) - T/l, reduce, one atomic per CTA ----
    float e = 0.f;
    if ((lane & 3) == 0)
        e = (__logf(l2[0]) - T2[0] / l2[0]) + (__logf(l2[1]) - T2[1] / l2[1]);
#pragma unroll
    for (int off = 16; off; off >>= 1) e += __shfl_xor_sync(0xffffffffu, e, off);
    if (lane == 0) red[wid] = e;
    __syncthreads();
    if (tid == 0) {
        float esum = red[0] + red[1] + red[2] + red[3];
        const float ent_scale = (float)(1.0 / (7.6246189861593985 * (double)(TH * TS)));
        atomicAdd(ent + b, esum * ent_scale);
    }
}

// ---------------------------------------------------------------------------
extern "C" void kernel_launch(void* const* d_in, const int* in_sizes, int n_in,
                              void* d_out, int out_size)
{
    const float* x       = (const float*)d_in[0];
    const float* w_qkv   = (const float*)d_in[1];
    const float* w_proj  = (const float*)d_in[2];
    const float* q_scale = (const float*)d_in[3];
    const float* q_bias  = (const float*)d_in[4];
    const float* k_scale = (const float*)d_in[5];
    const float* k_bias  = (const float*)d_in[6];
    float* out = (float*)d_out;

    float *qkv, *ctx, *entpad;
    cudaGetSymbolAddress((void**)&qkv, g_qkv);
    cudaGetSymbolAddress((void**)&ctx, g_ctx);
    cudaGetSymbolAddress((void**)&entpad, g_entpad);
    __half *xh, *xl, *wq, *ch, *cl, *wp;
    __half *qh2, *ql2, *kh2, *vh2, *vl2;
    cudaGetSymbolAddress((void**)&xh, g_xh);
    cudaGetSymbolAddress((void**)&xl, g_xl);
    cudaGetSymbolAddress((void**)&wq, g_wq);
    cudaGetSymbolAddress((void**)&ch, g_ch);
    cudaGetSymbolAddress((void**)&cl, g_cl);
    cudaGetSymbolAddress((void**)&wp, g_wp);
    cudaGetSymbolAddress((void**)&qh2, g_qh2);
    cudaGetSymbolAddress((void**)&ql2, g_ql2);
    cudaGetSymbolAddress((void**)&kh2, g_kh2);
    cudaGetSymbolAddress((void**)&vh2, g_vh2);
    cudaGetSymbolAddress((void**)&vl2, g_vl2);

    cudaFuncSetAttribute(gemm_mma_kernel, cudaFuncAttributeMaxDynamicSharedMemorySize, GEMM_SMEM);
    cudaFuncSetAttribute(attn_mma_kernel, cudaFuncAttributeMaxDynamicSharedMemorySize, ATTN_SMEM);

    const int BS = TB * TS;                 // 8192
    const size_t main_elems = (size_t)BS * TC;
    float* ent = (out_size >= (int)(main_elems + TB)) ? (out + main_elems) : entpad;

    // 1) split x -> fp16 hi/lo ; transpose w_qkv -> single fp16
    {
        int n4 = (BS * TC) / 4;
        split_kernel<<<(n4 + 255) / 256, 256>>>((const float4*)x, xh, xl, n4);
        splitTs_kernel<<<dim3(3 * TC / 32, TC / 32), dim3(32, 8)>>>(w_qkv, wq, TC, 3 * TC);
    }

    // 2) QKV projection (fp16x2 mma.sync): [8192,1024] @ [1024,3072]
    gemm_mma_kernel<<<dim3(3 * TC / 128, BS / 128), 256, GEMM_SMEM>>>(
        xh, xl, wq, qkv, BS, 3 * TC, TC);

    // 3) fused LayerNorm + split -> pre-split fp16 q/k/v in [b,h,s,d]
    ln_split_kernel<<<(TB * TS * TH) / 8, 256>>>(
        qkv, q_scale, q_bias, k_scale, k_bias, qh2, ql2, kh2, vh2, vl2);

    // 4) zero entropy accumulators
    zero4_kernel<<<1, TB>>>(ent);

    // 5) fused attention + entropy -> ctx fp32 (cp.async double-buffered)
    attn_mma_kernel<<<dim3(TS / 64, TH, TB), 128, ATTN_SMEM>>>(
        qh2, ql2, kh2, vh2, vl2, ctx, ent);

    // 6) split ctx ; transpose w_proj -> single fp16
    {
        int n4 = (BS * TC) / 4;
        split_kernel<<<(n4 + 255) / 256, 256>>>((const float4*)ctx, ch, cl, n4);
        splitTs_kernel<<<dim3(TC / 32, TC / 32), dim3(32, 8)>>>(w_proj, wp, TC, TC);
    }

    // 7) output projection (fp16x2): [8192,1024] @ [1024,1024]
    gemm_mma_kernel<<<dim3(TC / 128, BS / 128), 256, GEMM_SMEM>>>(
        ch, cl, wp, out, BS, TC, TC);
}

// round 9
// speedup vs baseline: 1.7743x; 1.2044x over previous
#include <cuda_runtime.h>
#include <cuda_fp16.h>
#include <cstdint>

#define TB 4
#define TS 2048
#define TH 16
#define TD 64
#define TC 1024

// ---------------------------------------------------------------------------
// Scratch (alloc-free rule: __device__ globals)
// ---------------------------------------------------------------------------
static __device__ float g_qkv[(size_t)8192 * 3072];          // [B*S, 3*C] fp32
static __device__ float g_ctx[(size_t)8192 * 1024];          // [B*S, C]   fp32
static __device__ float g_entpad[4];
// fp16 operands
static __device__ __half g_xh[(size_t)8192 * 1024];
static __device__ __half g_xl[(size_t)8192 * 1024];
static __device__ __half g_wq[(size_t)3072 * 1024];          // w_qkv^T [N,K] single
static __device__ __half g_cs[(size_t)8192 * 1024];          // ctx single fp16
static __device__ __half g_wp[(size_t)1024 * 1024];          // w_proj^T [N,K] single
// pre-split attention operands, [b,h,s,d] layout (contiguous 64-elem rows)
#define NBH ((size_t)TB * TH * TS * 64)
static __device__ __half g_qh2[NBH];
static __device__ __half g_ql2[NBH];
static __device__ __half g_kh2[NBH];                          // K single fp16
static __device__ __half g_vh2[NBH];                          // V single fp16

// ---------------------------------------------------------------------------
// Helpers (sm_103 base target: ldmatrix + mma.sync + cp.async only)
// ---------------------------------------------------------------------------
__device__ __forceinline__ uint32_t smem_u32(const void* p) {
    uint32_t a;
    asm("{ .reg .u64 t; cvta.to.shared.u64 t, %1; cvt.u32.u64 %0, t; }" : "=r"(a) : "l"(p));
    return a;
}
__device__ __forceinline__ uint32_t sw128(uint32_t off) { return off ^ ((off >> 3) & 0x70); }

__device__ __forceinline__ void cp16(uint32_t saddr, const void* gptr) {
    asm volatile("cp.async.cg.shared.global [%0], [%1], 16;" :: "r"(saddr), "l"(gptr));
}
__device__ __forceinline__ void cp_commit() {
    asm volatile("cp.async.commit_group;" ::: "memory");
}
template <int N>
__device__ __forceinline__ void cp_wait() {
    asm volatile("cp.async.wait_group %0;" :: "n"(N) : "memory");
}

__device__ __forceinline__ void ldm_x4(uint32_t addr, uint32_t r[4]) {
    asm volatile("ldmatrix.sync.aligned.m8n8.x4.shared.b16 {%0,%1,%2,%3}, [%4];"
                 : "=r"(r[0]), "=r"(r[1]), "=r"(r[2]), "=r"(r[3]) : "r"(addr));
}
__device__ __forceinline__ void ldm_x4_t(uint32_t addr, uint32_t r[4]) {
    asm volatile("ldmatrix.sync.aligned.m8n8.x4.trans.shared.b16 {%0,%1,%2,%3}, [%4];"
                 : "=r"(r[0]), "=r"(r[1]), "=r"(r[2]), "=r"(r[3]) : "r"(addr));
}

__device__ __forceinline__ void mma16816(float d[4], const uint32_t a[4], const uint32_t b[2]) {
    asm volatile(
        "mma.sync.aligned.m16n8k16.row.col.f32.f16.f16.f32 "
        "{%0,%1,%2,%3}, {%4,%5,%6,%7}, {%8,%9}, {%0,%1,%2,%3};"
        : "+f"(d[0]), "+f"(d[1]), "+f"(d[2]), "+f"(d[3])
        : "r"(a[0]), "r"(a[1]), "r"(a[2]), "r"(a[3]), "r"(b[0]), "r"(b[1]));
}

// pack two floats into fp16x2 (a = low, b = high)
__device__ __forceinline__ uint32_t cvt2h(float a, float b) {
    __half2 h = __floats2half2_rn(a, b);
    return *(uint32_t*)&h;
}
// split two floats into packed fp16x2 hi + lo halves
__device__ __forceinline__ void split2h(float a, float b, uint32_t& hi, uint32_t& lo) {
    __half2 h = __floats2half2_rn(a, b);
    float ra = a - __low2float(h);
    float rb = b - __high2float(h);
    __half2 l = __floats2half2_rn(ra, rb);
    hi = *(uint32_t*)&h;
    lo = *(uint32_t*)&l;
}

// ---------------------------------------------------------------------------
// Conversion kernels
// ---------------------------------------------------------------------------
__global__ __launch_bounds__(256) void split_kernel(
    const float4* __restrict__ in, __half* __restrict__ hi,
    __half* __restrict__ lo, int n4)
{
    int i = blockIdx.x * 256 + threadIdx.x;
    if (i >= n4) return;
    float4 v = in[i];
    uint32_t h01, h23, l01, l23;
    split2h(v.x, v.y, h01, l01);
    split2h(v.z, v.w, h23, l23);
    ((uint2*)hi)[i] = make_uint2(h01, h23);
    ((uint2*)lo)[i] = make_uint2(l01, l23);
}

// fp32 -> single fp16
__global__ __launch_bounds__(256) void cvt_kernel(
    const float4* __restrict__ in, __half* __restrict__ out, int n4)
{
    int i = blockIdx.x * 256 + threadIdx.x;
    if (i >= n4) return;
    float4 v = in[i];
    ((uint2*)out)[i] = make_uint2(cvt2h(v.x, v.y), cvt2h(v.z, v.w));
}

// Transpose + single fp16: in f32 [K,N] -> fp16 [N,K]
__global__ __launch_bounds__(256) void splitTs_kernel(
    const float* __restrict__ in, __half* __restrict__ hi, int K, int N)
{
    __shared__ float t[32][33];
    const int n0 = blockIdx.x << 5;
    const int k0 = blockIdx.y << 5;
    const int tx = threadIdx.x, ty = threadIdx.y;   // 32 x 8
#pragma unroll
    for (int j = 0; j < 32; j += 8)
        t[ty + j][tx] = in[(size_t)(k0 + ty + j) * N + n0 + tx];
    __syncthreads();
#pragma unroll
    for (int j = 0; j < 32; j += 8) {
        size_t o = (size_t)(n0 + ty + j) * K + k0 + tx;
        hi[o] = __float2half_rn(t[tx][ty + j]);
    }
}

// ---------------------------------------------------------------------------
// Warp-MMA fp16x2 GEMM: C[M,N] = (Ah+Al)[M,K] @ B[N,K]^T  (B single fp16)
// ---------------------------------------------------------------------------
#define GSM_AH 0
#define GSM_AL 16384
#define GSM_B  32768
#define GSM_BUF 49152
#define GEMM_SMEM (2 * GSM_BUF)

__global__ __launch_bounds__(256) void gemm_mma_kernel(
    const __half* __restrict__ Ah, const __half* __restrict__ Al,
    const __half* __restrict__ B, float* __restrict__ C, int M, int N, int K)
{
    extern __shared__ char smem[];
    const uint32_t sb = smem_u32(smem);
    const int tid = threadIdx.x;
    const int wid = tid >> 5;
    const int lane = tid & 31;
    const int row0 = blockIdx.y << 7;
    const int col0 = blockIdx.x << 7;
    const int wm = (wid & 1) << 6;
    const int wn = (wid >> 1) << 5;

    const int lr0 = tid >> 1;
    const int lk0 = (tid & 1) << 2;

    float acc[4][4][4];
#pragma unroll
    for (int mt = 0; mt < 4; ++mt)
#pragma unroll
        for (int nt = 0; nt < 4; ++nt)
#pragma unroll
            for (int r = 0; r < 4; ++r) acc[mt][nt][r] = 0.f;

    const int nk = K >> 6;

    auto load_tile = [&](int kb, int buf) {
        const uint32_t s0 = sb + buf * GSM_BUF;
#pragma unroll
        for (int cc = 0; cc < 4; ++cc) {
            const int r = lr0;
            const int k8 = lk0 + cc;
            const size_t offA = (size_t)(row0 + r) * K + kb + (k8 << 3);
            const size_t offB = (size_t)(col0 + r) * K + kb + (k8 << 3);
            const uint32_t so = sw128((uint32_t)((r << 7) + (k8 << 4)));
            cp16(s0 + GSM_AH + so, Ah + offA);
            cp16(s0 + GSM_AL + so, Al + offA);
            cp16(s0 + GSM_B + so, B + offB);
        }
        cp_commit();
    };

    load_tile(0, 0);

    const int la_r = lane & 15;
    const int la_c = lane >> 4;
    const int lb_r = ((lane >> 4) << 3) + (lane & 7);
    const int lb_c = (lane >> 3) & 1;

    for (int it = 0; it < nk; ++it) {
        if (it + 1 < nk) { load_tile((it + 1) << 6, (it + 1) & 1); cp_wait<1>(); }
        else             { cp_wait<0>(); }
        __syncthreads();
        const uint32_t s0 = sb + (it & 1) * GSM_BUF;

#pragma unroll
        for (int ks = 0; ks < 4; ++ks) {
            uint32_t ah[4][4], al[4][4], bh[2][4];
#pragma unroll
            for (int mt = 0; mt < 4; ++mt) {
                const uint32_t so =
                    sw128((uint32_t)(((wm + (mt << 4) + la_r) << 7) + (((ks << 1) + la_c) << 4)));
                ldm_x4(s0 + GSM_AH + so, ah[mt]);
                ldm_x4(s0 + GSM_AL + so, al[mt]);
            }
#pragma unroll
            for (int p = 0; p < 2; ++p) {
                const uint32_t so =
                    sw128((uint32_t)(((wn + (p << 4) + lb_r) << 7) + (((ks << 1) + lb_c) << 4)));
                ldm_x4(s0 + GSM_B + so, bh[p]);
            }
#pragma unroll
            for (int mt = 0; mt < 4; ++mt)
#pragma unroll
                for (int nt = 0; nt < 4; ++nt) {
                    const uint32_t* bp = &bh[nt >> 1][(nt & 1) << 1];
                    mma16816(acc[mt][nt], ah[mt], bp);
                    mma16816(acc[mt][nt], al[mt], bp);
                }
        }
        __syncthreads();
    }

    const int g = lane >> 2, tg = lane & 3;
#pragma unroll
    for (int mt = 0; mt < 4; ++mt)
#pragma unroll
        for (int nt = 0; nt < 4; ++nt) {
            const int row = row0 + wm + (mt << 4) + g;
            const int col = col0 + wn + (nt << 3) + (tg << 1);
            *(float2*)(C + (size_t)row * N + col) = make_float2(acc[mt][nt][0], acc[mt][nt][1]);
            *(float2*)(C + (size_t)(row + 8) * N + col) = make_float2(acc[mt][nt][2], acc[mt][nt][3]);
        }
}

// ---------------------------------------------------------------------------
// Single-precision-operand fp16 GEMM: C[M,N] = A[M,K] @ B[N,K]^T (both single)
// Smem 2 arrays/stage (32KB), 2 stages = 64KB -> 3 CTAs/SM.
// ---------------------------------------------------------------------------
#define SS_A 0
#define SS_B 16384
#define SS_BUF 32768
#define GEMM_S_SMEM (2 * SS_BUF)

__global__ __launch_bounds__(256) void gemm_s_kernel(
    const __half* __restrict__ A, const __half* __restrict__ B,
    float* __restrict__ C, int M, int N, int K)
{
    extern __shared__ char smem[];
    const uint32_t sb = smem_u32(smem);
    const int tid = threadIdx.x;
    const int wid = tid >> 5;
    const int lane = tid & 31;
    const int row0 = blockIdx.y << 7;
    const int col0 = blockIdx.x << 7;
    const int wm = (wid & 1) << 6;
    const int wn = (wid >> 1) << 5;

    const int lr0 = tid >> 1;
    const int lk0 = (tid & 1) << 2;

    float acc[4][4][4];
#pragma unroll
    for (int mt = 0; mt < 4; ++mt)
#pragma unroll
        for (int nt = 0; nt < 4; ++nt)
#pragma unroll
            for (int r = 0; r < 4; ++r) acc[mt][nt][r] = 0.f;

    const int nk = K >> 6;

    auto load_tile = [&](int kb, int buf) {
        const uint32_t s0 = sb + buf * SS_BUF;
#pragma unroll
        for (int cc = 0; cc < 4; ++cc) {
            const int r = lr0;
            const int k8 = lk0 + cc;
            const size_t offA = (size_t)(row0 + r) * K + kb + (k8 << 3);
            const size_t offB = (size_t)(col0 + r) * K + kb + (k8 << 3);
            const uint32_t so = sw128((uint32_t)((r << 7) + (k8 << 4)));
            cp16(s0 + SS_A + so, A + offA);
            cp16(s0 + SS_B + so, B + offB);
        }
        cp_commit();
    };

    load_tile(0, 0);

    const int la_r = lane & 15;
    const int la_c = lane >> 4;
    const int lb_r = ((lane >> 4) << 3) + (lane & 7);
    const int lb_c = (lane >> 3) & 1;

    for (int it = 0; it < nk; ++it) {
        if (it + 1 < nk) { load_tile((it + 1) << 6, (it + 1) & 1); cp_wait<1>(); }
        else             { cp_wait<0>(); }
        __syncthreads();
        const uint32_t s0 = sb + (it & 1) * SS_BUF;

#pragma unroll
        for (int ks = 0; ks < 4; ++ks) {
            uint32_t ah[4][4], bh[2][4];
#pragma unroll
            for (int mt = 0; mt < 4; ++mt) {
                const uint32_t so =
                    sw128((uint32_t)(((wm + (mt << 4) + la_r) << 7) + (((ks << 1) + la_c) << 4)));
                ldm_x4(s0 + SS_A + so, ah[mt]);
            }
#pragma unroll
            for (int p = 0; p < 2; ++p) {
                const uint32_t so =
                    sw128((uint32_t)(((wn + (p << 4) + lb_r) << 7) + (((ks << 1) + lb_c) << 4)));
                ldm_x4(s0 + SS_B + so, bh[p]);
            }
#pragma unroll
            for (int mt = 0; mt < 4; ++mt)
#pragma unroll
                for (int nt = 0; nt < 4; ++nt)
                    mma16816(acc[mt][nt], ah[mt], &bh[nt >> 1][(nt & 1) << 1]);
        }
        __syncthreads();
    }

    const int g = lane >> 2, tg = lane & 3;
#pragma unroll
    for (int mt = 0; mt < 4; ++mt)
#pragma unroll
        for (int nt = 0; nt < 4; ++nt) {
            const int row = row0 + wm + (mt << 4) + g;
            const int col = col0 + wn + (nt << 3) + (tg << 1);
            *(float2*)(C + (size_t)row * N + col) = make_float2(acc[mt][nt][0], acc[mt][nt][1]);
            *(float2*)(C + (size_t)(row + 8) * N + col) = make_float2(acc[mt][nt][2], acc[mt][nt][3]);
        }
}

// ---------------------------------------------------------------------------
// Fused LayerNorm + split: qkv fp32 [b,s,3,h,d] ->
//   q: LN, *0.125, fp16 split -> qh/ql [b,h,s,d]
//   k: LN, single fp16 -> kh ; v: single fp16 -> vh
// ---------------------------------------------------------------------------
__global__ __launch_bounds__(256) void ln_split_kernel(
    const float* __restrict__ qkv,
    const float* __restrict__ qs, const float* __restrict__ qbias,
    const float* __restrict__ ks, const float* __restrict__ kbias,
    __half* __restrict__ qh, __half* __restrict__ ql,
    __half* __restrict__ kh, __half* __restrict__ vh)
{
    const int w = (int)((blockIdx.x * 256u + threadIdx.x) >> 5);   // row over B*S*H
    const int lane = threadIdx.x & 31;
    const int h = w & 15;
    const int bs = w >> 4;
    const int b = bs >> 11, s = bs & 2047;
    const float* p = qkv + (size_t)bs * 3072 + h * 64 + lane * 2;

    float2 qv = *(const float2*)p;
    float2 kv = *(const float2*)(p + 1024);
    float2 vv = *(const float2*)(p + 2048);

    float sq = qv.x + qv.y, qq = qv.x * qv.x + qv.y * qv.y;
    float sk = kv.x + kv.y, kk = kv.x * kv.x + kv.y * kv.y;
#pragma unroll
    for (int off = 16; off; off >>= 1) {
        sq += __shfl_xor_sync(0xffffffffu, sq, off);
        qq += __shfl_xor_sync(0xffffffffu, qq, off);
        sk += __shfl_xor_sync(0xffffffffu, sk, off);
        kk += __shfl_xor_sync(0xffffffffu, kk, off);
    }
    float qm = sq * (1.f / 64.f);
    float qr = rsqrtf(fmaxf(qq * (1.f / 64.f) - qm * qm, 0.f) + 1e-5f);
    float km = sk * (1.f / 64.f);
    float kr = rsqrtf(fmaxf(kk * (1.f / 64.f) - km * km, 0.f) + 1e-5f);

    float2 scq = *(const float2*)(qs + lane * 2);
    float2 biq = *(const float2*)(qbias + lane * 2);
    float2 sck = *(const float2*)(ks + lane * 2);
    float2 bik = *(const float2*)(kbias + lane * 2);

    float qnx = ((qv.x - qm) * qr * scq.x + biq.x) * 0.125f;
    float qny = ((qv.y - qm) * qr * scq.y + biq.y) * 0.125f;
    float knx = (kv.x - km) * kr * sck.x + bik.x;
    float kny = (kv.y - km) * kr * sck.y + bik.y;

    const size_t o = (((size_t)(b * TH + h)) * TS + s) * 64 + lane * 2;
    uint32_t hw, lw;
    split2h(qnx, qny, hw, lw);
    *(uint32_t*)(qh + o) = hw; *(uint32_t*)(ql + o) = lw;
    *(uint32_t*)(kh + o) = cvt2h(knx, kny);
    *(uint32_t*)(vh + o) = cvt2h(vv.x, vv.y);
}

__global__ void zero4_kernel(float* p) { p[threadIdx.x] = 0.f; }

// ---------------------------------------------------------------------------
// Flash attention on mma.sync (fp16) + streaming entropy.
// CTA: 64 q-rows, 4 warps (warp = m16 x n64), 128 threads. K-tile = 64 keys.
// S = (Qh+Ql)·K (K single) ; O += P(single)·V (V single).
// Smem: double-buffered {K, V} (16KB/stage) + persistent Q hi/lo (16KB) = 48KB.
// ---------------------------------------------------------------------------
#define AB_K  0
#define AB_VH 8192
#define AB_BUF 16384
#define AQ_H 32768
#define AQ_L 40960
#define ATTN_SMEM 49152

__global__ __launch_bounds__(128) void attn_mma_kernel(
    const __half* __restrict__ qhg, const __half* __restrict__ qlg,
    const __half* __restrict__ khg, const __half* __restrict__ vhg,
    float* __restrict__ ctx, float* __restrict__ ent)
{
    extern __shared__ char smA[];
    __shared__ float red[4];
    const uint32_t sb = smem_u32(smA);

    const int tid = threadIdx.x, wid = tid >> 5, lane = tid & 31;
    const int qb0 = blockIdx.x << 6;           // 64 q rows per CTA
    const int h = blockIdx.y, b = blockIdx.z;
    const size_t bh = ((size_t)(b * TH + h)) * TS * 64;

    // ---- prologue: Q -> persistent region (group 0) ----
#pragma unroll
    for (int j = 0; j < 4; ++j) {
        int c = tid + 128 * j;                 // 512 chunks per array
        int row = c >> 3, k8 = c & 7;
        size_t g = bh + (size_t)(qb0 + row) * 64 + (k8 << 3);
        uint32_t so = sw128((uint32_t)((row << 7) + (k8 << 4)));
        cp16(sb + AQ_H + so, qhg + g);
        cp16(sb + AQ_L + so, qlg + g);
    }
    cp_commit();

    auto load_kv = [&](int kt) {
        const uint32_t bufb = sb + (uint32_t)(kt & 1) * AB_BUF;
#pragma unroll
        for (int j = 0; j < 4; ++j) {
            int c = tid + 128 * j;
            int row = c >> 3, k8 = c & 7;
            size_t g = bh + (size_t)((kt << 6) + row) * 64 + (k8 << 3);
            uint32_t so = sw128((uint32_t)((row << 7) + (k8 << 4)));
            cp16(bufb + AB_K + so, khg + g);
            cp16(bufb + AB_VH + so, vhg + g);
        }
        cp_commit();
    };
    load_kv(0);                                // tile 0 (group 1)

    cp_wait<1>();                              // Q group retired (FIFO)
    __syncthreads();

    // ---- extract Q A-fragments (hi/lo) ----
    uint32_t qh[4][4], ql[4][4];
    {
        const int row = (wid << 4) + (lane & 15);
        const int cb = (lane >> 4) << 4;
#pragma unroll
        for (int s = 0; s < 4; ++s) {
            uint32_t so = sw128((uint32_t)(row * 128 + s * 32 + cb));
            ldm_x4(sb + AQ_H + so, qh[s]);
            ldm_x4(sb + AQ_L + so, ql[s]);
        }
    }

    float o[8][4];
#pragma unroll
    for (int nt = 0; nt < 8; ++nt)
#pragma unroll
        for (int r = 0; r < 4; ++r) o[nt][r] = 0.f;
    float m2[2] = {-1e30f, -1e30f}, l2[2] = {0.f, 0.f}, T2[2] = {0.f, 0.f};

    const int kb_row = ((lane >> 4) << 3) + (lane & 7);
    const int kb_c = (lane >> 3) & 1;
    const int v_key = (((lane >> 3) & 1) << 3) + (lane & 7);
    const int v_d = (lane >> 4) << 3;

    for (int kt = 0; kt < TS / 64; ++kt) {
        if (kt + 1 < TS / 64) { load_kv(kt + 1); cp_wait<1>(); }
        else                  { cp_wait<0>(); }
        __syncthreads();
        const uint32_t bufb = sb + (uint32_t)(kt & 1) * AB_BUF;

        // ---- S = Q K^T (K single) ----
        float s4[8][4];
#pragma unroll
        for (int nt = 0; nt < 8; ++nt)
#pragma unroll
            for (int r = 0; r < 4; ++r) s4[nt][r] = 0.f;

#pragma unroll
        for (int s = 0; s < 4; ++s) {
            uint32_t kb[4][4];
#pragma unroll
            for (int p = 0; p < 4; ++p) {
                uint32_t so = sw128((uint32_t)(((p << 4) + kb_row) * 128 + s * 32 + kb_c * 16));
                ldm_x4(bufb + AB_K + so, kb[p]);
            }
#pragma unroll
            for (int nt = 0; nt < 8; ++nt) {
                const uint32_t* kb2 = &kb[nt >> 1][(nt & 1) << 1];
                mma16816(s4[nt], qh[s], kb2);
                mma16816(s4[nt], ql[s], kb2);
            }
        }

        // ---- online softmax + entropy terms (rows g, g+8 per thread) ----
        float mx0 = s4[0][0], mx1 = s4[0][2];
#pragma unroll
        for (int nt = 0; nt < 8; ++nt) {
            mx0 = fmaxf(mx0, fmaxf(s4[nt][0], s4[nt][1]));
            mx1 = fmaxf(mx1, fmaxf(s4[nt][2], s4[nt][3]));
        }
#pragma unroll
        for (int off = 1; off <= 2; off <<= 1) {
            mx0 = fmaxf(mx0, __shfl_xor_sync(0xffffffffu, mx0, off));
            mx1 = fmaxf(mx1, __shfl_xor_sync(0xffffffffu, mx1, off));
        }
        float mn0 = fmaxf(m2[0], mx0), mn1 = fmaxf(m2[1], mx1);
        float ls0 = 0.f, ts0 = 0.f, ls1 = 0.f, ts1 = 0.f;
#pragma unroll
        for (int nt = 0; nt < 8; ++nt) {
            float d0 = s4[nt][0] - mn0, d1 = s4[nt][1] - mn0;
            float d2 = s4[nt][2] - mn1, d3 = s4[nt][3] - mn1;
            float e0 = __expf(d0), e1 = __expf(d1), e2 = __expf(d2), e3 = __expf(d3);
            s4[nt][0] = e0; s4[nt][1] = e1; s4[nt][2] = e2; s4[nt][3] = e3;
            ls0 += e0 + e1; ls1 += e2 + e3;
            ts0 = fmaf(e0, d0, fmaf(e1, d1, ts0));
            ts1 = fmaf(e2, d2, fmaf(e3, d3, ts1));
        }
#pragma unroll
        for (int off = 1; off <= 2; off <<= 1) {
            ls0 += __shfl_xor_sync(0xffffffffu, ls0, off);
            ts0 += __shfl_xor_sync(0xffffffffu, ts0, off);
            ls1 += __shfl_xor_sync(0xffffffffu, ls1, off);
            ts1 += __shfl_xor_sync(0xffffffffu, ts1, off);
        }
        float dm0 = mn0 - m2[0], c0 = __expf(-dm0);
        float dm1 = mn1 - m2[1], c1 = __expf(-dm1);
        T2[0] = fmaf(c0, T2[0] - dm0 * l2[0], ts0);
        T2[1] = fmaf(c1, T2[1] - dm1 * l2[1], ts1);
        l2[0] = fmaf(l2[0], c0, ls0);
        l2[1] = fmaf(l2[1], c1, ls1);
        m2[0] = mn0; m2[1] = mn1;
#pragma unroll
        for (int nt = 0; nt < 8; ++nt) {
            o[nt][0] *= c0; o[nt][1] *= c0;
            o[nt][2] *= c1; o[nt][3] *= c1;
        }

        // ---- O += P V (P single fp16; V single via ldmatrix.trans) ----
#pragma unroll
        for (int s = 0; s < 4; ++s) {
            uint32_t pa[4];
            pa[0] = cvt2h(s4[2 * s][0],     s4[2 * s][1]);
            pa[1] = cvt2h(s4[2 * s][2],     s4[2 * s][3]);
            pa[2] = cvt2h(s4[2 * s + 1][0], s4[2 * s + 1][1]);
            pa[3] = cvt2h(s4[2 * s + 1][2], s4[2 * s + 1][3]);
            uint32_t vb[4][4];
#pragma unroll
            for (int p2 = 0; p2 < 4; ++p2) {
                uint32_t so = sw128((uint32_t)(((s << 4) + v_key) * 128 + ((p2 << 4) + v_d) * 2));
                ldm_x4_t(bufb + AB_VH + so, vb[p2]);
            }
#pragma unroll
            for (int nt = 0; nt < 8; ++nt)
                mma16816(o[nt], pa, &vb[nt >> 1][(nt & 1) << 1]);
        }
        __syncthreads();   // all warps done reading buf before next overwrite
    }

    // ---- write context fp32 ----
    {
        float rl0 = 1.f / l2[0], rl1 = 1.f / l2[1];
        const int r0 = qb0 + (wid << 4) + (lane >> 2);
        const int cb = (h << 6) + ((lane & 3) << 1);
#pragma unroll
        for (int nt = 0; nt < 8; ++nt) {
            const int col = cb + (nt << 3);
            *(float2*)(ctx + (size_t)(b * TS + r0) * 1024 + col) =
                make_float2(o[nt][0] * rl0, o[nt][1] * rl0);
            *(float2*)(ctx + (size_t)(b * TS + r0 + 8) * 1024 + col) =
                make_float2(o[nt][2] * rl1, o[nt][3] * rl1);
        }
    }

    // ---- entropy: per-row log(l) - T/l, reduce, one atomic per CTA ----
    float e = 0.f;
    if ((lane & 3) == 0)
        e = (__logf(l2[0]) - T2[0] / l2[0]) + (__logf(l2[1]) - T2[1] / l2[1]);
#pragma unroll
    for (int off = 16; off; off >>= 1) e += __shfl_xor_sync(0xffffffffu, e, off);
    if (lane == 0) red[wid] = e;
    __syncthreads();
    if (tid == 0) {
        float esum = red[0] + red[1] + red[2] + red[3];
        const float ent_scale = (float)(1.0 / (7.6246189861593985 * (double)(TH * TS)));
        atomicAdd(ent + b, esum * ent_scale);
    }
}

// ---------------------------------------------------------------------------
extern "C" void kernel_launch(void* const* d_in, const int* in_sizes, int n_in,
                              void* d_out, int out_size)
{
    const float* x       = (const float*)d_in[0];
    const float* w_qkv   = (const float*)d_in[1];
    const float* w_proj  = (const float*)d_in[2];
    const float* q_scale = (const float*)d_in[3];
    const float* q_bias  = (const float*)d_in[4];
    const float* k_scale = (const float*)d_in[5];
    const float* k_bias  = (const float*)d_in[6];
    float* out = (float*)d_out;

    float *qkv, *ctx, *entpad;
    cudaGetSymbolAddress((void**)&qkv, g_qkv);
    cudaGetSymbolAddress((void**)&ctx, g_ctx);
    cudaGetSymbolAddress((void**)&entpad, g_entpad);
    __half *xh, *xl, *wq, *cs, *wp;
    __half *qh2, *ql2, *kh2, *vh2;
    cudaGetSymbolAddress((void**)&xh, g_xh);
    cudaGetSymbolAddress((void**)&xl, g_xl);
    cudaGetSymbolAddress((void**)&wq, g_wq);
    cudaGetSymbolAddress((void**)&cs, g_cs);
    cudaGetSymbolAddress((void**)&wp, g_wp);
    cudaGetSymbolAddress((void**)&qh2, g_qh2);
    cudaGetSymbolAddress((void**)&ql2, g_ql2);
    cudaGetSymbolAddress((void**)&kh2, g_kh2);
    cudaGetSymbolAddress((void**)&vh2, g_vh2);

    cudaFuncSetAttribute(gemm_mma_kernel, cudaFuncAttributeMaxDynamicSharedMemorySize, GEMM_SMEM);
    cudaFuncSetAttribute(gemm_s_kernel, cudaFuncAttributeMaxDynamicSharedMemorySize, GEMM_S_SMEM);
    cudaFuncSetAttribute(attn_mma_kernel, cudaFuncAttributeMaxDynamicSharedMemorySize, ATTN_SMEM);

    const int BS = TB * TS;                 // 8192
    const size_t main_elems = (size_t)BS * TC;
    float* ent = (out_size >= (int)(main_elems + TB)) ? (out + main_elems) : entpad;

    // 1) split x -> fp16 hi/lo ; transpose w_qkv -> single fp16
    {
        int n4 = (BS * TC) / 4;
        split_kernel<<<(n4 + 255) / 256, 256>>>((const float4*)x, xh, xl, n4);
        splitTs_kernel<<<dim3(3 * TC / 32, TC / 32), dim3(32, 8)>>>(w_qkv, wq, TC, 3 * TC);
    }

    // 2) QKV projection (fp16x2 mma.sync): [8192,1024] @ [1024,3072]
    gemm_mma_kernel<<<dim3(3 * TC / 128, BS / 128), 256, GEMM_SMEM>>>(
        xh, xl, wq, qkv, BS, 3 * TC, TC);

    // 3) fused LayerNorm + split -> fp16 q(hi/lo)/k/v in [b,h,s,d]
    ln_split_kernel<<<(TB * TS * TH) / 8, 256>>>(
        qkv, q_scale, q_bias, k_scale, k_bias, qh2, ql2, kh2, vh2);

    // 4) zero entropy accumulators
    zero4_kernel<<<1, TB>>>(ent);

    // 5) fused attention + entropy -> ctx fp32 (cp.async double-buffered)
    attn_mma_kernel<<<dim3(TS / 64, TH, TB), 128, ATTN_SMEM>>>(
        qh2, ql2, kh2, vh2, ctx, ent);

    // 6) ctx -> single fp16 ; transpose w_proj -> single fp16
    {
        int n4 = (BS * TC) / 4;
        cvt_kernel<<<(n4 + 255) / 256, 256>>>((const float4*)ctx, cs, n4);
        splitTs_kernel<<<dim3(TC / 32, TC / 32), dim3(32, 8)>>>(w_proj, wp, TC, TC);
    }

    // 7) output projection (single fp16 x single fp16): [8192,1024] @ [1024,1024]
    gemm_s_kernel<<<dim3(TC / 128, BS / 128), 256, GEMM_S_SMEM>>>(
        cs, wp, out, BS, TC, TC);
}

// round 10
// speedup vs baseline: 2.2777x; 1.2837x over previous
#include <cuda_runtime.h>
#include <cuda_fp16.h>
#include <cstdint>

#define TB 4
#define TS 2048
#define TH 16
#define TD 64
#define TC 1024

// ---------------------------------------------------------------------------
// Scratch (alloc-free rule: __device__ globals)
// ---------------------------------------------------------------------------
static __device__ float g_qkv[(size_t)8192 * 3072];          // [B*S, 3*C] fp32
static __device__ float g_ctx[(size_t)8192 * 1024];          // [B*S, C]   fp32
static __device__ float g_entpad[4];
// fp16 operands (all single except attention Q hi/lo)
static __device__ __half g_xs[(size_t)8192 * 1024];          // x single fp16
static __device__ __half g_wq[(size_t)3072 * 1024];          // w_qkv^T [N,K] single
static __device__ __half g_cs[(size_t)8192 * 1024];          // ctx single fp16
static __device__ __half g_wp[(size_t)1024 * 1024];          // w_proj^T [N,K] single
// pre-split attention operands, [b,h,s,d] layout (contiguous 64-elem rows)
#define NBH ((size_t)TB * TH * TS * 64)
static __device__ __half g_qh2[NBH];
static __device__ __half g_ql2[NBH];
static __device__ __half g_kh2[NBH];                          // K single fp16
static __device__ __half g_vh2[NBH];                          // V single fp16

// ---------------------------------------------------------------------------
// Helpers (sm_103 base target: ldmatrix + mma.sync + cp.async only)
// ---------------------------------------------------------------------------
__device__ __forceinline__ uint32_t smem_u32(const void* p) {
    uint32_t a;
    asm("{ .reg .u64 t; cvta.to.shared.u64 t, %1; cvt.u32.u64 %0, t; }" : "=r"(a) : "l"(p));
    return a;
}
__device__ __forceinline__ uint32_t sw128(uint32_t off) { return off ^ ((off >> 3) & 0x70); }

__device__ __forceinline__ void cp16(uint32_t saddr, const void* gptr) {
    asm volatile("cp.async.cg.shared.global [%0], [%1], 16;" :: "r"(saddr), "l"(gptr));
}
__device__ __forceinline__ void cp_commit() {
    asm volatile("cp.async.commit_group;" ::: "memory");
}
template <int N>
__device__ __forceinline__ void cp_wait() {
    asm volatile("cp.async.wait_group %0;" :: "n"(N) : "memory");
}

__device__ __forceinline__ void ldm_x4(uint32_t addr, uint32_t r[4]) {
    asm volatile("ldmatrix.sync.aligned.m8n8.x4.shared.b16 {%0,%1,%2,%3}, [%4];"
                 : "=r"(r[0]), "=r"(r[1]), "=r"(r[2]), "=r"(r[3]) : "r"(addr));
}
__device__ __forceinline__ void ldm_x4_t(uint32_t addr, uint32_t r[4]) {
    asm volatile("ldmatrix.sync.aligned.m8n8.x4.trans.shared.b16 {%0,%1,%2,%3}, [%4];"
                 : "=r"(r[0]), "=r"(r[1]), "=r"(r[2]), "=r"(r[3]) : "r"(addr));
}

__device__ __forceinline__ void mma16816(float d[4], const uint32_t a[4], const uint32_t b[2]) {
    asm volatile(
        "mma.sync.aligned.m16n8k16.row.col.f32.f16.f16.f32 "
        "{%0,%1,%2,%3}, {%4,%5,%6,%7}, {%8,%9}, {%0,%1,%2,%3};"
        : "+f"(d[0]), "+f"(d[1]), "+f"(d[2]), "+f"(d[3])
        : "r"(a[0]), "r"(a[1]), "r"(a[2]), "r"(a[3]), "r"(b[0]), "r"(b[1]));
}

// pack two floats into fp16x2 (a = low, b = high)
__device__ __forceinline__ uint32_t cvt2h(float a, float b) {
    __half2 h = __floats2half2_rn(a, b);
    return *(uint32_t*)&h;
}
// split two floats into packed fp16x2 hi + lo halves
__device__ __forceinline__ void split2h(float a, float b, uint32_t& hi, uint32_t& lo) {
    __half2 h = __floats2half2_rn(a, b);
    float ra = a - __low2float(h);
    float rb = b - __high2float(h);
    __half2 l = __floats2half2_rn(ra, rb);
    hi = *(uint32_t*)&h;
    lo = *(uint32_t*)&l;
}

// ---------------------------------------------------------------------------
// Conversion kernels
// ---------------------------------------------------------------------------
// fp32 -> single fp16
__global__ __launch_bounds__(256) void cvt_kernel(
    const float4* __restrict__ in, __half* __restrict__ out, int n4)
{
    int i = blockIdx.x * 256 + threadIdx.x;
    if (i >= n4) return;
    float4 v = in[i];
    ((uint2*)out)[i] = make_uint2(cvt2h(v.x, v.y), cvt2h(v.z, v.w));
}

// Transpose + single fp16: in f32 [K,N] -> fp16 [N,K]
__global__ __launch_bounds__(256) void splitTs_kernel(
    const float* __restrict__ in, __half* __restrict__ hi, int K, int N)
{
    __shared__ float t[32][33];
    const int n0 = blockIdx.x << 5;
    const int k0 = blockIdx.y << 5;
    const int tx = threadIdx.x, ty = threadIdx.y;   // 32 x 8
#pragma unroll
    for (int j = 0; j < 32; j += 8)
        t[ty + j][tx] = in[(size_t)(k0 + ty + j) * N + n0 + tx];
    __syncthreads();
#pragma unroll
    for (int j = 0; j < 32; j += 8) {
        size_t o = (size_t)(n0 + ty + j) * K + k0 + tx;
        hi[o] = __float2half_rn(t[tx][ty + j]);
    }
}

// ---------------------------------------------------------------------------
// Single-operand fp16 GEMM: C[M,N] = A[M,K] @ B[N,K]^T (both single fp16)
// CTA 128x128, K-tile 64, 8 warps; smem 2 arrays/stage (32KB), 2 stages.
// ---------------------------------------------------------------------------
#define SS_A 0
#define SS_B 16384
#define SS_BUF 32768
#define GEMM_S_SMEM (2 * SS_BUF)

__global__ __launch_bounds__(256) void gemm_s_kernel(
    const __half* __restrict__ A, const __half* __restrict__ B,
    float* __restrict__ C, int M, int N, int K)
{
    extern __shared__ char smem[];
    const uint32_t sb = smem_u32(smem);
    const int tid = threadIdx.x;
    const int wid = tid >> 5;
    const int lane = tid & 31;
    const int row0 = blockIdx.y << 7;
    const int col0 = blockIdx.x << 7;
    const int wm = (wid & 1) << 6;
    const int wn = (wid >> 1) << 5;

    const int lr0 = tid >> 1;
    const int lk0 = (tid & 1) << 2;

    float acc[4][4][4];
#pragma unroll
    for (int mt = 0; mt < 4; ++mt)
#pragma unroll
        for (int nt = 0; nt < 4; ++nt)
#pragma unroll
            for (int r = 0; r < 4; ++r) acc[mt][nt][r] = 0.f;

    const int nk = K >> 6;

    auto load_tile = [&](int kb, int buf) {
        const uint32_t s0 = sb + buf * SS_BUF;
#pragma unroll
        for (int cc = 0; cc < 4; ++cc) {
            const int r = lr0;
            const int k8 = lk0 + cc;
            const size_t offA = (size_t)(row0 + r) * K + kb + (k8 << 3);
            const size_t offB = (size_t)(col0 + r) * K + kb + (k8 << 3);
            const uint32_t so = sw128((uint32_t)((r << 7) + (k8 << 4)));
            cp16(s0 + SS_A + so, A + offA);
            cp16(s0 + SS_B + so, B + offB);
        }
        cp_commit();
    };

    load_tile(0, 0);

    const int la_r = lane & 15;
    const int la_c = lane >> 4;
    const int lb_r = ((lane >> 4) << 3) + (lane & 7);
    const int lb_c = (lane >> 3) & 1;

    for (int it = 0; it < nk; ++it) {
        if (it + 1 < nk) { load_tile((it + 1) << 6, (it + 1) & 1); cp_wait<1>(); }
        else             { cp_wait<0>(); }
        __syncthreads();
        const uint32_t s0 = sb + (it & 1) * SS_BUF;

#pragma unroll
        for (int ks = 0; ks < 4; ++ks) {
            uint32_t ah[4][4], bh[2][4];
#pragma unroll
            for (int mt = 0; mt < 4; ++mt) {
                const uint32_t so =
                    sw128((uint32_t)(((wm + (mt << 4) + la_r) << 7) + (((ks << 1) + la_c) << 4)));
                ldm_x4(s0 + SS_A + so, ah[mt]);
            }
#pragma unroll
            for (int p = 0; p < 2; ++p) {
                const uint32_t so =
                    sw128((uint32_t)(((wn + (p << 4) + lb_r) << 7) + (((ks << 1) + lb_c) << 4)));
                ldm_x4(s0 + SS_B + so, bh[p]);
            }
#pragma unroll
            for (int mt = 0; mt < 4; ++mt)
#pragma unroll
                for (int nt = 0; nt < 4; ++nt)
                    mma16816(acc[mt][nt], ah[mt], &bh[nt >> 1][(nt & 1) << 1]);
        }
        __syncthreads();
    }

    const int g = lane >> 2, tg = lane & 3;
#pragma unroll
    for (int mt = 0; mt < 4; ++mt)
#pragma unroll
        for (int nt = 0; nt < 4; ++nt) {
            const int row = row0 + wm + (mt << 4) + g;
            const int col = col0 + wn + (nt << 3) + (tg << 1);
            *(float2*)(C + (size_t)row * N + col) = make_float2(acc[mt][nt][0], acc[mt][nt][1]);
            *(float2*)(C + (size_t)(row + 8) * N + col) = make_float2(acc[mt][nt][2], acc[mt][nt][3]);
        }
}

// ---------------------------------------------------------------------------
// Fused LayerNorm + split: qkv fp32 [b,s,3,h,d] ->
//   q: LN, *0.125, fp16 split -> qh/ql [b,h,s,d]
//   k: LN, single fp16 -> kh ; v: single fp16 -> vh
// ---------------------------------------------------------------------------
__global__ __launch_bounds__(256) void ln_split_kernel(
    const float* __restrict__ qkv,
    const float* __restrict__ qs, const float* __restrict__ qbias,
    const float* __restrict__ ks, const float* __restrict__ kbias,
    __half* __restrict__ qh, __half* __restrict__ ql,
    __half* __restrict__ kh, __half* __restrict__ vh)
{
    const int w = (int)((blockIdx.x * 256u + threadIdx.x) >> 5);   // row over B*S*H
    const int lane = threadIdx.x & 31;
    const int h = w & 15;
    const int bs = w >> 4;
    const int b = bs >> 11, s = bs & 2047;
    const float* p = qkv + (size_t)bs * 3072 + h * 64 + lane * 2;

    float2 qv = *(const float2*)p;
    float2 kv = *(const float2*)(p + 1024);
    float2 vv = *(const float2*)(p + 2048);

    float sq = qv.x + qv.y, qq = qv.x * qv.x + qv.y * qv.y;
    float sk = kv.x + kv.y, kk = kv.x * kv.x + kv.y * kv.y;
#pragma unroll
    for (int off = 16; off; off >>= 1) {
        sq += __shfl_xor_sync(0xffffffffu, sq, off);
        qq += __shfl_xor_sync(0xffffffffu, qq, off);
        sk += __shfl_xor_sync(0xffffffffu, sk, off);
        kk += __shfl_xor_sync(0xffffffffu, kk, off);
    }
    float qm = sq * (1.f / 64.f);
    float qr = rsqrtf(fmaxf(qq * (1.f / 64.f) - qm * qm, 0.f) + 1e-5f);
    float km = sk * (1.f / 64.f);
    float kr = rsqrtf(fmaxf(kk * (1.f / 64.f) - km * km, 0.f) + 1e-5f);

    float2 scq = *(const float2*)(qs + lane * 2);
    float2 biq = *(const float2*)(qbias + lane * 2);
    float2 sck = *(const float2*)(ks + lane * 2);
    float2 bik = *(const float2*)(kbias + lane * 2);

    float qnx = ((qv.x - qm) * qr * scq.x + biq.x) * 0.125f;
    float qny = ((qv.y - qm) * qr * scq.y + biq.y) * 0.125f;
    float knx = (kv.x - km) * kr * sck.x + bik.x;
    float kny = (kv.y - km) * kr * sck.y + bik.y;

    const size_t o = (((size_t)(b * TH + h)) * TS + s) * 64 + lane * 2;
    uint32_t hw, lw;
    split2h(qnx, qny, hw, lw);
    *(uint32_t*)(qh + o) = hw; *(uint32_t*)(ql + o) = lw;
    *(uint32_t*)(kh + o) = cvt2h(knx, kny);
    *(uint32_t*)(vh + o) = cvt2h(vv.x, vv.y);
}

__global__ void zero4_kernel(float* p) { p[threadIdx.x] = 0.f; }

// ---------------------------------------------------------------------------
// Flash attention on mma.sync (fp16) + streaming entropy.
// CTA: 64 q-rows, 4 warps (warp = m16 x n64), 128 threads. K-tile = 64 keys.
// S = (Qh+Ql)·K (K single) ; O += P(single)·V (V single).
// Smem: double-buffered {K, V} (16KB/stage) + persistent Q hi/lo (16KB) = 48KB.
// ---------------------------------------------------------------------------
#define AB_K  0
#define AB_VH 8192
#define AB_BUF 16384
#define AQ_H 32768
#define AQ_L 40960
#define ATTN_SMEM 49152

__global__ __launch_bounds__(128) void attn_mma_kernel(
    const __half* __restrict__ qhg, const __half* __restrict__ qlg,
    const __half* __restrict__ khg, const __half* __restrict__ vhg,
    float* __restrict__ ctx, float* __restrict__ ent)
{
    extern __shared__ char smA[];
    __shared__ float red[4];
    const uint32_t sb = smem_u32(smA);

    const int tid = threadIdx.x, wid = tid >> 5, lane = tid & 31;
    const int qb0 = blockIdx.x << 6;           // 64 q rows per CTA
    const int h = blockIdx.y, b = blockIdx.z;
    const size_t bh = ((size_t)(b * TH + h)) * TS * 64;

    // ---- prologue: Q -> persistent region (group 0) ----
#pragma unroll
    for (int j = 0; j < 4; ++j) {
        int c = tid + 128 * j;                 // 512 chunks per array
        int row = c >> 3, k8 = c & 7;
        size_t g = bh + (size_t)(qb0 + row) * 64 + (k8 << 3);
        uint32_t so = sw128((uint32_t)((row << 7) + (k8 << 4)));
        cp16(sb + AQ_H + so, qhg + g);
        cp16(sb + AQ_L + so, qlg + g);
    }
    cp_commit();

    auto load_kv = [&](int kt) {
        const uint32_t bufb = sb + (uint32_t)(kt & 1) * AB_BUF;
#pragma unroll
        for (int j = 0; j < 4; ++j) {
            int c = tid + 128 * j;
            int row = c >> 3, k8 = c & 7;
            size_t g = bh + (size_t)((kt << 6) + row) * 64 + (k8 << 3);
            uint32_t so = sw128((uint32_t)((row << 7) + (k8 << 4)));
            cp16(bufb + AB_K + so, khg + g);
            cp16(bufb + AB_VH + so, vhg + g);
        }
        cp_commit();
    };
    load_kv(0);                                // tile 0 (group 1)

    cp_wait<1>();                              // Q group retired (FIFO)
    __syncthreads();

    // ---- extract Q A-fragments (hi/lo) ----
    uint32_t qh[4][4], ql[4][4];
    {
        const int row = (wid << 4) + (lane & 15);
        const int cb = (lane >> 4) << 4;
#pragma unroll
        for (int s = 0; s < 4; ++s) {
            uint32_t so = sw128((uint32_t)(row * 128 + s * 32 + cb));
            ldm_x4(sb + AQ_H + so, qh[s]);
            ldm_x4(sb + AQ_L + so, ql[s]);
        }
    }

    float o[8][4];
#pragma unroll
    for (int nt = 0; nt < 8; ++nt)
#pragma unroll
        for (int r = 0; r < 4; ++r) o[nt][r] = 0.f;
    float m2[2] = {-1e30f, -1e30f}, l2[2] = {0.f, 0.f}, T2[2] = {0.f, 0.f};

    const int kb_row = ((lane >> 4) << 3) + (lane & 7);
    const int kb_c = (lane >> 3) & 1;
    const int v_key = (((lane >> 3) & 1) << 3) + (lane & 7);
    const int v_d = (lane >> 4) << 3;

    for (int kt = 0; kt < TS / 64; ++kt) {
        if (kt + 1 < TS / 64) { load_kv(kt + 1); cp_wait<1>(); }
        else                  { cp_wait<0>(); }
        __syncthreads();
        const uint32_t bufb = sb + (uint32_t)(kt & 1) * AB_BUF;

        // ---- S = Q K^T (K single) ----
        float s4[8][4];
#pragma unroll
        for (int nt = 0; nt < 8; ++nt)
#pragma unroll
            for (int r = 0; r < 4; ++r) s4[nt][r] = 0.f;

#pragma unroll
        for (int s = 0; s < 4; ++s) {
            uint32_t kb[4][4];
#pragma unroll
            for (int p = 0; p < 4; ++p) {
                uint32_t so = sw128((uint32_t)(((p << 4) + kb_row) * 128 + s * 32 + kb_c * 16));
                ldm_x4(bufb + AB_K + so, kb[p]);
            }
#pragma unroll
            for (int nt = 0; nt < 8; ++nt) {
                const uint32_t* kb2 = &kb[nt >> 1][(nt & 1) << 1];
                mma16816(s4[nt], qh[s], kb2);
                mma16816(s4[nt], ql[s], kb2);
            }
        }

        // ---- online softmax + entropy terms (rows g, g+8 per thread) ----
        float mx0 = s4[0][0], mx1 = s4[0][2];
#pragma unroll
        for (int nt = 0; nt < 8; ++nt) {
            mx0 = fmaxf(mx0, fmaxf(s4[nt][0], s4[nt][1]));
            mx1 = fmaxf(mx1, fmaxf(s4[nt][2], s4[nt][3]));
        }
#pragma unroll
        for (int off = 1; off <= 2; off <<= 1) {
            mx0 = fmaxf(mx0, __shfl_xor_sync(0xffffffffu, mx0, off));
            mx1 = fmaxf(mx1, __shfl_xor_sync(0xffffffffu, mx1, off));
        }
        float mn0 = fmaxf(m2[0], mx0), mn1 = fmaxf(m2[1], mx1);
        float ls0 = 0.f, ts0 = 0.f, ls1 = 0.f, ts1 = 0.f;
#pragma unroll
        for (int nt = 0; nt < 8; ++nt) {
            float d0 = s4[nt][0] - mn0, d1 = s4[nt][1] - mn0;
            float d2 = s4[nt][2] - mn1, d3 = s4[nt][3] - mn1;
            float e0 = __expf(d0), e1 = __expf(d1), e2 = __expf(d2), e3 = __expf(d3);
            s4[nt][0] = e0; s4[nt][1] = e1; s4[nt][2] = e2; s4[nt][3] = e3;
            ls0 += e0 + e1; ls1 += e2 + e3;
            ts0 = fmaf(e0, d0, fmaf(e1, d1, ts0));
            ts1 = fmaf(e2, d2, fmaf(e3, d3, ts1));
        }
#pragma unroll
        for (int off = 1; off <= 2; off <<= 1) {
            ls0 += __shfl_xor_sync(0xffffffffu, ls0, off);
            ts0 += __shfl_xor_sync(0xffffffffu, ts0, off);
            ls1 += __shfl_xor_sync(0xffffffffu, ls1, off);
            ts1 += __shfl_xor_sync(0xffffffffu, ts1, off);
        }
        float dm0 = mn0 - m2[0], c0 = __expf(-dm0);
        float dm1 = mn1 - m2[1], c1 = __expf(-dm1);
        T2[0] = fmaf(c0, T2[0] - dm0 * l2[0], ts0);
        T2[1] = fmaf(c1, T2[1] - dm1 * l2[1], ts1);
        l2[0] = fmaf(l2[0], c0, ls0);
        l2[1] = fmaf(l2[1], c1, ls1);
        m2[0] = mn0; m2[1] = mn1;
#pragma unroll
        for (int nt = 0; nt < 8; ++nt) {
            o[nt][0] *= c0; o[nt][1] *= c0;
            o[nt][2] *= c1; o[nt][3] *= c1;
        }

        // ---- O += P V (P single fp16; V single via ldmatrix.trans) ----
#pragma unroll
        for (int s = 0; s < 4; ++s) {
            uint32_t pa[4];
            pa[0] = cvt2h(s4[2 * s][0],     s4[2 * s][1]);
            pa[1] = cvt2h(s4[2 * s][2],     s4[2 * s][3]);
            pa[2] = cvt2h(s4[2 * s + 1][0], s4[2 * s + 1][1]);
            pa[3] = cvt2h(s4[2 * s + 1][2], s4[2 * s + 1][3]);
            uint32_t vb[4][4];
#pragma unroll
            for (int p2 = 0; p2 < 4; ++p2) {
                uint32_t so = sw128((uint32_t)(((s << 4) + v_key) * 128 + ((p2 << 4) + v_d) * 2));
                ldm_x4_t(bufb + AB_VH + so, vb[p2]);
            }
#pragma unroll
            for (int nt = 0; nt < 8; ++nt)
                mma16816(o[nt], pa, &vb[nt >> 1][(nt & 1) << 1]);
        }
        __syncthreads();   // all warps done reading buf before next overwrite
    }

    // ---- write context fp32 ----
    {
        float rl0 = 1.f / l2[0], rl1 = 1.f / l2[1];
        const int r0 = qb0 + (wid << 4) + (lane >> 2);
        const int cb = (h << 6) + ((lane & 3) << 1);
#pragma unroll
        for (int nt = 0; nt < 8; ++nt) {
            const int col = cb + (nt << 3);
            *(float2*)(ctx + (size_t)(b * TS + r0) * 1024 + col) =
                make_float2(o[nt][0] * rl0, o[nt][1] * rl0);
            *(float2*)(ctx + (size_t)(b * TS + r0 + 8) * 1024 + col) =
                make_float2(o[nt][2] * rl1, o[nt][3] * rl1);
        }
    }

    // ---- entropy: per-row log(l) - T/l, reduce, one atomic per CTA ----
    float e = 0.f;
    if ((lane & 3) == 0)
        e = (__logf(l2[0]) - T2[0] / l2[0]) + (__logf(l2[1]) - T2[1] / l2[1]);
#pragma unroll
    for (int off = 16; off; off >>= 1) e += __shfl_xor_sync(0xffffffffu, e, off);
    if (lane == 0) red[wid] = e;
    __syncthreads();
    if (tid == 0) {
        float esum = red[0] + red[1] + red[2] + red[3];
        const float ent_scale = (float)(1.0 / (7.6246189861593985 * (double)(TH * TS)));
        atomicAdd(ent + b, esum * ent_scale);
    }
}

// ---------------------------------------------------------------------------
extern "C" void kernel_launch(void* const* d_in, const int* in_sizes, int n_in,
                              void* d_out, int out_size)
{
    const float* x       = (const float*)d_in[0];
    const float* w_qkv   = (const float*)d_in[1];
    const float* w_proj  = (const float*)d_in[2];
    const float* q_scale = (const float*)d_in[3];
    const float* q_bias  = (const float*)d_in[4];
    const float* k_scale = (const float*)d_in[5];
    const float* k_bias  = (const float*)d_in[6];
    float* out = (float*)d_out;

    float *qkv, *ctx, *entpad;
    cudaGetSymbolAddress((void**)&qkv, g_qkv);
    cudaGetSymbolAddress((void**)&ctx, g_ctx);
    cudaGetSymbolAddress((void**)&entpad, g_entpad);
    __half *xs, *wq, *cs, *wp;
    __half *qh2, *ql2, *kh2, *vh2;
    cudaGetSymbolAddress((void**)&xs, g_xs);
    cudaGetSymbolAddress((void**)&wq, g_wq);
    cudaGetSymbolAddress((void**)&cs, g_cs);
    cudaGetSymbolAddress((void**)&wp, g_wp);
    cudaGetSymbolAddress((void**)&qh2, g_qh2);
    cudaGetSymbolAddress((void**)&ql2, g_ql2);
    cudaGetSymbolAddress((void**)&kh2, g_kh2);
    cudaGetSymbolAddress((void**)&vh2, g_vh2);

    cudaFuncSetAttribute(gemm_s_kernel, cudaFuncAttributeMaxDynamicSharedMemorySize, GEMM_S_SMEM);
    cudaFuncSetAttribute(attn_mma_kernel, cudaFuncAttributeMaxDynamicSharedMemorySize, ATTN_SMEM);

    const int BS = TB * TS;                 // 8192
    const size_t main_elems = (size_t)BS * TC;
    float* ent = (out_size >= (int)(main_elems + TB)) ? (out + main_elems) : entpad;

    // 1) x -> single fp16 ; transpose w_qkv -> single fp16
    {
        int n4 = (BS * TC) / 4;
        cvt_kernel<<<(n4 + 255) / 256, 256>>>((const float4*)x, xs, n4);
        splitTs_kernel<<<dim3(3 * TC / 32, TC / 32), dim3(32, 8)>>>(w_qkv, wq, TC, 3 * TC);
    }

    // 2) QKV projection (single fp16 x single fp16): [8192,1024] @ [1024,3072]
    gemm_s_kernel<<<dim3(3 * TC / 128, BS / 128), 256, GEMM_S_SMEM>>>(
        xs, wq, qkv, BS, 3 * TC, TC);

    // 3) fused LayerNorm + split -> fp16 q(hi/lo)/k/v in [b,h,s,d]
    ln_split_kernel<<<(TB * TS * TH) / 8, 256>>>(
        qkv, q_scale, q_bias, k_scale, k_bias, qh2, ql2, kh2, vh2);

    // 4) zero entropy accumulators
    zero4_kernel<<<1, TB>>>(ent);

    // 5) fused attention + entropy -> ctx fp32 (cp.async double-buffered)
    attn_mma_kernel<<<dim3(TS / 64, TH, TB), 128, ATTN_SMEM>>>(
        qh2, ql2, kh2, vh2, ctx, ent);

    // 6) ctx -> single fp16 ; transpose w_proj -> single fp16
    {
        int n4 = (BS * TC) / 4;
        cvt_kernel<<<(n4 + 255) / 256, 256>>>((const float4*)ctx, cs, n4);
        splitTs_kernel<<<dim3(TC / 32, TC / 32), dim3(32, 8)>>>(w_proj, wp, TC, TC);
    }

    // 7) output projection (single fp16 x single fp16): [8192,1024] @ [1024,1024]
    gemm_s_kernel<<<dim3(TC / 128, BS / 128), 256, GEMM_S_SMEM>>>(
        cs, wp, out, BS, TC, TC);
}

// round 11
// speedup vs baseline: 2.5514x; 1.1202x over previous
#include <cuda_runtime.h>
#include <cuda_fp16.h>
#include <cstdint>

#define TB 4
#define TS 2048
#define TH 16
#define TD 64
#define TC 1024

// ---------------------------------------------------------------------------
// Scratch (alloc-free rule: __device__ globals)
// ---------------------------------------------------------------------------
static __device__ float g_qkv[(size_t)8192 * 3072];          // [B*S, 3*C] fp32
static __device__ float g_entpad[4];
// fp16 operands (all single precision now)
static __device__ __half g_xs[(size_t)8192 * 1024];          // x single fp16
static __device__ __half g_wq[(size_t)3072 * 1024];          // w_qkv^T [N,K] single
static __device__ __half g_cs[(size_t)8192 * 1024];          // ctx single fp16
static __device__ __half g_wp[(size_t)1024 * 1024];          // w_proj^T [N,K] single
// attention operands, [b,h,s,d] layout (contiguous 64-elem rows)
#define NBH ((size_t)TB * TH * TS * 64)
static __device__ __half g_qh2[NBH];                          // Q single fp16 (pre-scaled)
static __device__ __half g_kh2[NBH];                          // K single fp16
static __device__ __half g_vh2[NBH];                          // V single fp16

// ---------------------------------------------------------------------------
// Helpers (sm_103 base target: ldmatrix + mma.sync + cp.async only)
// ---------------------------------------------------------------------------
__device__ __forceinline__ uint32_t smem_u32(const void* p) {
    uint32_t a;
    asm("{ .reg .u64 t; cvta.to.shared.u64 t, %1; cvt.u32.u64 %0, t; }" : "=r"(a) : "l"(p));
    return a;
}
__device__ __forceinline__ uint32_t sw128(uint32_t off) { return off ^ ((off >> 3) & 0x70); }

__device__ __forceinline__ void cp16(uint32_t saddr, const void* gptr) {
    asm volatile("cp.async.cg.shared.global [%0], [%1], 16;" :: "r"(saddr), "l"(gptr));
}
__device__ __forceinline__ void cp_commit() {
    asm volatile("cp.async.commit_group;" ::: "memory");
}
template <int N>
__device__ __forceinline__ void cp_wait() {
    asm volatile("cp.async.wait_group %0;" :: "n"(N) : "memory");
}

__device__ __forceinline__ void ldm_x4(uint32_t addr, uint32_t r[4]) {
    asm volatile("ldmatrix.sync.aligned.m8n8.x4.shared.b16 {%0,%1,%2,%3}, [%4];"
                 : "=r"(r[0]), "=r"(r[1]), "=r"(r[2]), "=r"(r[3]) : "r"(addr));
}
__device__ __forceinline__ void ldm_x4_t(uint32_t addr, uint32_t r[4]) {
    asm volatile("ldmatrix.sync.aligned.m8n8.x4.trans.shared.b16 {%0,%1,%2,%3}, [%4];"
                 : "=r"(r[0]), "=r"(r[1]), "=r"(r[2]), "=r"(r[3]) : "r"(addr));
}

__device__ __forceinline__ void mma16816(float d[4], const uint32_t a[4], const uint32_t b[2]) {
    asm volatile(
        "mma.sync.aligned.m16n8k16.row.col.f32.f16.f16.f32 "
        "{%0,%1,%2,%3}, {%4,%5,%6,%7}, {%8,%9}, {%0,%1,%2,%3};"
        : "+f"(d[0]), "+f"(d[1]), "+f"(d[2]), "+f"(d[3])
        : "r"(a[0]), "r"(a[1]), "r"(a[2]), "r"(a[3]), "r"(b[0]), "r"(b[1]));
}

// pack two floats into fp16x2 (a = low, b = high)
__device__ __forceinline__ uint32_t cvt2h(float a, float b) {
    __half2 h = __floats2half2_rn(a, b);
    return *(uint32_t*)&h;
}

// ---------------------------------------------------------------------------
// Conversion kernels
// ---------------------------------------------------------------------------
// fp32 -> single fp16
__global__ __launch_bounds__(256) void cvt_kernel(
    const float4* __restrict__ in, __half* __restrict__ out, int n4)
{
    int i = blockIdx.x * 256 + threadIdx.x;
    if (i >= n4) return;
    float4 v = in[i];
    ((uint2*)out)[i] = make_uint2(cvt2h(v.x, v.y), cvt2h(v.z, v.w));
}

// Transpose + single fp16: in f32 [K,N] -> fp16 [N,K]
__global__ __launch_bounds__(256) void splitTs_kernel(
    const float* __restrict__ in, __half* __restrict__ hi, int K, int N)
{
    __shared__ float t[32][33];
    const int n0 = blockIdx.x << 5;
    const int k0 = blockIdx.y << 5;
    const int tx = threadIdx.x, ty = threadIdx.y;   // 32 x 8
#pragma unroll
    for (int j = 0; j < 32; j += 8)
        t[ty + j][tx] = in[(size_t)(k0 + ty + j) * N + n0 + tx];
    __syncthreads();
#pragma unroll
    for (int j = 0; j < 32; j += 8) {
        size_t o = (size_t)(n0 + ty + j) * K + k0 + tx;
        hi[o] = __float2half_rn(t[tx][ty + j]);
    }
}

// ---------------------------------------------------------------------------
// Single-operand fp16 GEMM: C[M,N] = A[M,K] @ B[N,K]^T (both single fp16)
// CTA 128x128, K-tile 64, 8 warps; smem 2 arrays/stage (32KB), 2 stages.
// ---------------------------------------------------------------------------
#define SS_A 0
#define SS_B 16384
#define SS_BUF 32768
#define GEMM_S_SMEM (2 * SS_BUF)

__global__ __launch_bounds__(256) void gemm_s_kernel(
    const __half* __restrict__ A, const __half* __restrict__ B,
    float* __restrict__ C, int M, int N, int K)
{
    extern __shared__ char smem[];
    const uint32_t sb = smem_u32(smem);
    const int tid = threadIdx.x;
    const int wid = tid >> 5;
    const int lane = tid & 31;
    const int row0 = blockIdx.y << 7;
    const int col0 = blockIdx.x << 7;
    const int wm = (wid & 1) << 6;
    const int wn = (wid >> 1) << 5;

    const int lr0 = tid >> 1;
    const int lk0 = (tid & 1) << 2;

    float acc[4][4][4];
#pragma unroll
    for (int mt = 0; mt < 4; ++mt)
#pragma unroll
        for (int nt = 0; nt < 4; ++nt)
#pragma unroll
            for (int r = 0; r < 4; ++r) acc[mt][nt][r] = 0.f;

    const int nk = K >> 6;

    auto load_tile = [&](int kb, int buf) {
        const uint32_t s0 = sb + buf * SS_BUF;
#pragma unroll
        for (int cc = 0; cc < 4; ++cc) {
            const int r = lr0;
            const int k8 = lk0 + cc;
            const size_t offA = (size_t)(row0 + r) * K + kb + (k8 << 3);
            const size_t offB = (size_t)(col0 + r) * K + kb + (k8 << 3);
            const uint32_t so = sw128((uint32_t)((r << 7) + (k8 << 4)));
            cp16(s0 + SS_A + so, A + offA);
            cp16(s0 + SS_B + so, B + offB);
        }
        cp_commit();
    };

    load_tile(0, 0);

    const int la_r = lane & 15;
    const int la_c = lane >> 4;
    const int lb_r = ((lane >> 4) << 3) + (lane & 7);
    const int lb_c = (lane >> 3) & 1;

    for (int it = 0; it < nk; ++it) {
        if (it + 1 < nk) { load_tile((it + 1) << 6, (it + 1) & 1); cp_wait<1>(); }
        else             { cp_wait<0>(); }
        __syncthreads();
        const uint32_t s0 = sb + (it & 1) * SS_BUF;

#pragma unroll
        for (int ks = 0; ks < 4; ++ks) {
            uint32_t ah[4][4], bh[2][4];
#pragma unroll
            for (int mt = 0; mt < 4; ++mt) {
                const uint32_t so =
                    sw128((uint32_t)(((wm + (mt << 4) + la_r) << 7) + (((ks << 1) + la_c) << 4)));
                ldm_x4(s0 + SS_A + so, ah[mt]);
            }
#pragma unroll
            for (int p = 0; p < 2; ++p) {
                const uint32_t so =
                    sw128((uint32_t)(((wn + (p << 4) + lb_r) << 7) + (((ks << 1) + lb_c) << 4)));
                ldm_x4(s0 + SS_B + so, bh[p]);
            }
#pragma unroll
            for (int mt = 0; mt < 4; ++mt)
#pragma unroll
                for (int nt = 0; nt < 4; ++nt)
                    mma16816(acc[mt][nt], ah[mt], &bh[nt >> 1][(nt & 1) << 1]);
        }
        __syncthreads();
    }

    const int g = lane >> 2, tg = lane & 3;
#pragma unroll
    for (int mt = 0; mt < 4; ++mt)
#pragma unroll
        for (int nt = 0; nt < 4; ++nt) {
            const int row = row0 + wm + (mt << 4) + g;
            const int col = col0 + wn + (nt << 3) + (tg << 1);
            *(float2*)(C + (size_t)row * N + col) = make_float2(acc[mt][nt][0], acc[mt][nt][1]);
            *(float2*)(C + (size_t)(row + 8) * N + col) = make_float2(acc[mt][nt][2], acc[mt][nt][3]);
        }
}

// ---------------------------------------------------------------------------
// Fused LayerNorm + convert: qkv fp32 [b,s,3,h,d] ->
//   q: LN, *0.125, single fp16 -> qh [b,h,s,d]
//   k: LN, single fp16 -> kh ; v: single fp16 -> vh
// ---------------------------------------------------------------------------
__global__ __launch_bounds__(256) void ln_split_kernel(
    const float* __restrict__ qkv,
    const float* __restrict__ qs, const float* __restrict__ qbias,
    const float* __restrict__ ks, const float* __restrict__ kbias,
    __half* __restrict__ qh, __half* __restrict__ kh, __half* __restrict__ vh)
{
    const int w = (int)((blockIdx.x * 256u + threadIdx.x) >> 5);   // row over B*S*H
    const int lane = threadIdx.x & 31;
    const int h = w & 15;
    const int bs = w >> 4;
    const int b = bs >> 11, s = bs & 2047;
    const float* p = qkv + (size_t)bs * 3072 + h * 64 + lane * 2;

    float2 qv = *(const float2*)p;
    float2 kv = *(const float2*)(p + 1024);
    float2 vv = *(const float2*)(p + 2048);

    float sq = qv.x + qv.y, qq = qv.x * qv.x + qv.y * qv.y;
    float sk = kv.x + kv.y, kk = kv.x * kv.x + kv.y * kv.y;
#pragma unroll
    for (int off = 16; off; off >>= 1) {
        sq += __shfl_xor_sync(0xffffffffu, sq, off);
        qq += __shfl_xor_sync(0xffffffffu, qq, off);
        sk += __shfl_xor_sync(0xffffffffu, sk, off);
        kk += __shfl_xor_sync(0xffffffffu, kk, off);
    }
    float qm = sq * (1.f / 64.f);
    float qr = rsqrtf(fmaxf(qq * (1.f / 64.f) - qm * qm, 0.f) + 1e-5f);
    float km = sk * (1.f / 64.f);
    float kr = rsqrtf(fmaxf(kk * (1.f / 64.f) - km * km, 0.f) + 1e-5f);

    float2 scq = *(const float2*)(qs + lane * 2);
    float2 biq = *(const float2*)(qbias + lane * 2);
    float2 sck = *(const float2*)(ks + lane * 2);
    float2 bik = *(const float2*)(kbias + lane * 2);

    float qnx = ((qv.x - qm) * qr * scq.x + biq.x) * 0.125f;
    float qny = ((qv.y - qm) * qr * scq.y + biq.y) * 0.125f;
    float knx = (kv.x - km) * kr * sck.x + bik.x;
    float kny = (kv.y - km) * kr * sck.y + bik.y;

    const size_t o = (((size_t)(b * TH + h)) * TS + s) * 64 + lane * 2;
    *(uint32_t*)(qh + o) = cvt2h(qnx, qny);
    *(uint32_t*)(kh + o) = cvt2h(knx, kny);
    *(uint32_t*)(vh + o) = cvt2h(vv.x, vv.y);
}

__global__ void zero4_kernel(float* p) { p[threadIdx.x] = 0.f; }

// ---------------------------------------------------------------------------
// Flash attention on mma.sync (single fp16 everywhere) + streaming entropy.
// CTA: 64 q-rows, 4 warps (warp = m16 x n64), 128 threads. K-tile = 64 keys.
// S = Q·K ; O += P·V  (all single fp16 operands, fp32 accum).
// Smem: double-buffered {K, V} (16KB/stage) + persistent Q (8KB) = 40KB.
// Epilogue writes ctx as single fp16 (feeds proj GEMM directly).
// ---------------------------------------------------------------------------
#define AB_K  0
#define AB_VH 8192
#define AB_BUF 16384
#define AQ_H 32768
#define ATTN_SMEM 40960

__global__ __launch_bounds__(128) void attn_mma_kernel(
    const __half* __restrict__ qhg, const __half* __restrict__ khg,
    const __half* __restrict__ vhg,
    __half* __restrict__ cs, float* __restrict__ ent)
{
    extern __shared__ char smA[];
    __shared__ float red[4];
    const uint32_t sb = smem_u32(smA);

    const int tid = threadIdx.x, wid = tid >> 5, lane = tid & 31;
    const int qb0 = blockIdx.x << 6;           // 64 q rows per CTA
    const int h = blockIdx.y, b = blockIdx.z;
    const size_t bh = ((size_t)(b * TH + h)) * TS * 64;

    // ---- prologue: Q -> persistent region (group 0) ----
#pragma unroll
    for (int j = 0; j < 4; ++j) {
        int c = tid + 128 * j;                 // 512 chunks
        int row = c >> 3, k8 = c & 7;
        size_t g = bh + (size_t)(qb0 + row) * 64 + (k8 << 3);
        uint32_t so = sw128((uint32_t)((row << 7) + (k8 << 4)));
        cp16(sb + AQ_H + so, qhg + g);
    }
    cp_commit();

    auto load_kv = [&](int kt) {
        const uint32_t bufb = sb + (uint32_t)(kt & 1) * AB_BUF;
#pragma unroll
        for (int j = 0; j < 4; ++j) {
            int c = tid + 128 * j;
            int row = c >> 3, k8 = c & 7;
            size_t g = bh + (size_t)((kt << 6) + row) * 64 + (k8 << 3);
            uint32_t so = sw128((uint32_t)((row << 7) + (k8 << 4)));
            cp16(bufb + AB_K + so, khg + g);
            cp16(bufb + AB_VH + so, vhg + g);
        }
        cp_commit();
    };
    load_kv(0);                                // tile 0 (group 1)

    cp_wait<1>();                              // Q group retired (FIFO)
    __syncthreads();

    // ---- extract Q A-fragments ----
    uint32_t qh[4][4];
    {
        const int row = (wid << 4) + (lane & 15);
        const int cb = (lane >> 4) << 4;
#pragma unroll
        for (int s = 0; s < 4; ++s) {
            uint32_t so = sw128((uint32_t)(row * 128 + s * 32 + cb));
            ldm_x4(sb + AQ_H + so, qh[s]);
        }
    }

    float o[8][4];
#pragma unroll
    for (int nt = 0; nt < 8; ++nt)
#pragma unroll
        for (int r = 0; r < 4; ++r) o[nt][r] = 0.f;
    float m2[2] = {-1e30f, -1e30f}, l2[2] = {0.f, 0.f}, T2[2] = {0.f, 0.f};

    const int kb_row = ((lane >> 4) << 3) + (lane & 7);
    const int kb_c = (lane >> 3) & 1;
    const int v_key = (((lane >> 3) & 1) << 3) + (lane & 7);
    const int v_d = (lane >> 4) << 3;

    for (int kt = 0; kt < TS / 64; ++kt) {
        if (kt + 1 < TS / 64) { load_kv(kt + 1); cp_wait<1>(); }
        else                  { cp_wait<0>(); }
        __syncthreads();
        const uint32_t bufb = sb + (uint32_t)(kt & 1) * AB_BUF;

        // ---- S = Q K^T (single fp16) ----
        float s4[8][4];
#pragma unroll
        for (int nt = 0; nt < 8; ++nt)
#pragma unroll
            for (int r = 0; r < 4; ++r) s4[nt][r] = 0.f;

#pragma unroll
        for (int s = 0; s < 4; ++s) {
            uint32_t kb[4][4];
#pragma unroll
            for (int p = 0; p < 4; ++p) {
                uint32_t so = sw128((uint32_t)(((p << 4) + kb_row) * 128 + s * 32 + kb_c * 16));
                ldm_x4(bufb + AB_K + so, kb[p]);
            }
#pragma unroll
            for (int nt = 0; nt < 8; ++nt)
                mma16816(s4[nt], qh[s], &kb[nt >> 1][(nt & 1) << 1]);
        }

        // ---- online softmax + entropy terms (rows g, g+8 per thread) ----
        float mx0 = s4[0][0], mx1 = s4[0][2];
#pragma unroll
        for (int nt = 0; nt < 8; ++nt) {
            mx0 = fmaxf(mx0, fmaxf(s4[nt][0], s4[nt][1]));
            mx1 = fmaxf(mx1, fmaxf(s4[nt][2], s4[nt][3]));
        }
#pragma unroll
        for (int off = 1; off <= 2; off <<= 1) {
            mx0 = fmaxf(mx0, __shfl_xor_sync(0xffffffffu, mx0, off));
            mx1 = fmaxf(mx1, __shfl_xor_sync(0xffffffffu, mx1, off));
        }
        float mn0 = fmaxf(m2[0], mx0), mn1 = fmaxf(m2[1], mx1);
        float ls0 = 0.f, ts0 = 0.f, ls1 = 0.f, ts1 = 0.f;
#pragma unroll
        for (int nt = 0; nt < 8; ++nt) {
            float d0 = s4[nt][0] - mn0, d1 = s4[nt][1] - mn0;
            float d2 = s4[nt][2] - mn1, d3 = s4[nt][3] - mn1;
            float e0 = __expf(d0), e1 = __expf(d1), e2 = __expf(d2), e3 = __expf(d3);
            s4[nt][0] = e0; s4[nt][1] = e1; s4[nt][2] = e2; s4[nt][3] = e3;
            ls0 += e0 + e1; ls1 += e2 + e3;
            ts0 = fmaf(e0, d0, fmaf(e1, d1, ts0));
            ts1 = fmaf(e2, d2, fmaf(e3, d3, ts1));
        }
#pragma unroll
        for (int off = 1; off <= 2; off <<= 1) {
            ls0 += __shfl_xor_sync(0xffffffffu, ls0, off);
            ts0 += __shfl_xor_sync(0xffffffffu, ts0, off);
            ls1 += __shfl_xor_sync(0xffffffffu, ls1, off);
            ts1 += __shfl_xor_sync(0xffffffffu, ts1, off);
        }
        float dm0 = mn0 - m2[0], c0 = __expf(-dm0);
        float dm1 = mn1 - m2[1], c1 = __expf(-dm1);
        T2[0] = fmaf(c0, T2[0] - dm0 * l2[0], ts0);
        T2[1] = fmaf(c1, T2[1] - dm1 * l2[1], ts1);
        l2[0] = fmaf(l2[0], c0, ls0);
        l2[1] = fmaf(l2[1], c1, ls1);
        m2[0] = mn0; m2[1] = mn1;
#pragma unroll
        for (int nt = 0; nt < 8; ++nt) {
            o[nt][0] *= c0; o[nt][1] *= c0;
            o[nt][2] *= c1; o[nt][3] *= c1;
        }

        // ---- O += P V (P single fp16; V single via ldmatrix.trans) ----
#pragma unroll
        for (int s = 0; s < 4; ++s) {
            uint32_t pa[4];
            pa[0] = cvt2h(s4[2 * s][0],     s4[2 * s][1]);
            pa[1] = cvt2h(s4[2 * s][2],     s4[2 * s][3]);
            pa[2] = cvt2h(s4[2 * s + 1][0], s4[2 * s + 1][1]);
            pa[3] = cvt2h(s4[2 * s + 1][2], s4[2 * s + 1][3]);
            uint32_t vb[4][4];
#pragma unroll
            for (int p2 = 0; p2 < 4; ++p2) {
                uint32_t so = sw128((uint32_t)(((s << 4) + v_key) * 128 + ((p2 << 4) + v_d) * 2));
                ldm_x4_t(bufb + AB_VH + so, vb[p2]);
            }
#pragma unroll
            for (int nt = 0; nt < 8; ++nt)
                mma16816(o[nt], pa, &vb[nt >> 1][(nt & 1) << 1]);
        }
        __syncthreads();   // all warps done reading buf before next overwrite
    }

    // ---- write context as single fp16 (feeds proj GEMM directly) ----
    {
        float rl0 = 1.f / l2[0], rl1 = 1.f / l2[1];
        const int r0 = qb0 + (wid << 4) + (lane >> 2);
        const int cb = (h << 6) + ((lane & 3) << 1);
#pragma unroll
        for (int nt = 0; nt < 8; ++nt) {
            const int col = cb + (nt << 3);
            const size_t i0 = ((size_t)(b * TS + r0) * 1024 + col) >> 1;
            const size_t i1 = ((size_t)(b * TS + r0 + 8) * 1024 + col) >> 1;
            ((uint32_t*)cs)[i0] = cvt2h(o[nt][0] * rl0, o[nt][1] * rl0);
            ((uint32_t*)cs)[i1] = cvt2h(o[nt][2] * rl1, o[nt][3] * rl1);
        }
    }

    // ---- entropy: per-row log(l) - T/l, reduce, one atomic per CTA ----
    float e = 0.f;
    if ((lane & 3) == 0)
        e = (__logf(l2[0]) - T2[0] / l2[0]) + (__logf(l2[1]) - T2[1] / l2[1]);
#pragma unroll
    for (int off = 16; off; off >>= 1) e += __shfl_xor_sync(0xffffffffu, e, off);
    if (lane == 0) red[wid] = e;
    __syncthreads();
    if (tid == 0) {
        float esum = red[0] + red[1] + red[2] + red[3];
        const float ent_scale = (float)(1.0 / (7.6246189861593985 * (double)(TH * TS)));
        atomicAdd(ent + b, esum * ent_scale);
    }
}

// ---------------------------------------------------------------------------
extern "C" void kernel_launch(void* const* d_in, const int* in_sizes, int n_in,
                              void* d_out, int out_size)
{
    const float* x       = (const float*)d_in[0];
    const float* w_qkv   = (const float*)d_in[1];
    const float* w_proj  = (const float*)d_in[2];
    const float* q_scale = (const float*)d_in[3];
    const float* q_bias  = (const float*)d_in[4];
    const float* k_scale = (const float*)d_in[5];
    const float* k_bias  = (const float*)d_in[6];
    float* out = (float*)d_out;

    float *qkv, *entpad;
    cudaGetSymbolAddress((void**)&qkv, g_qkv);
    cudaGetSymbolAddress((void**)&entpad, g_entpad);
    __half *xs, *wq, *cs, *wp;
    __half *qh2, *kh2, *vh2;
    cudaGetSymbolAddress((void**)&xs, g_xs);
    cudaGetSymbolAddress((void**)&wq, g_wq);
    cudaGetSymbolAddress((void**)&cs, g_cs);
    cudaGetSymbolAddress((void**)&wp, g_wp);
    cudaGetSymbolAddress((void**)&qh2, g_qh2);
    cudaGetSymbolAddress((void**)&kh2, g_kh2);
    cudaGetSymbolAddress((void**)&vh2, g_vh2);

    cudaFuncSetAttribute(gemm_s_kernel, cudaFuncAttributeMaxDynamicSharedMemorySize, GEMM_S_SMEM);
    cudaFuncSetAttribute(attn_mma_kernel, cudaFuncAttributeMaxDynamicSharedMemorySize, ATTN_SMEM);

    const int BS = TB * TS;                 // 8192
    const size_t main_elems = (size_t)BS * TC;
    float* ent = (out_size >= (int)(main_elems + TB)) ? (out + main_elems) : entpad;

    // 1) x -> single fp16 ; transpose w_qkv -> single fp16
    {
        int n4 = (BS * TC) / 4;
        cvt_kernel<<<(n4 + 255) / 256, 256>>>((const float4*)x, xs, n4);
        splitTs_kernel<<<dim3(3 * TC / 32, TC / 32), dim3(32, 8)>>>(w_qkv, wq, TC, 3 * TC);
    }

    // 2) QKV projection (single fp16): [8192,1024] @ [1024,3072]
    gemm_s_kernel<<<dim3(3 * TC / 128, BS / 128), 256, GEMM_S_SMEM>>>(
        xs, wq, qkv, BS, 3 * TC, TC);

    // 3) fused LayerNorm + convert -> fp16 q/k/v in [b,h,s,d]
    ln_split_kernel<<<(TB * TS * TH) / 8, 256>>>(
        qkv, q_scale, q_bias, k_scale, k_bias, qh2, kh2, vh2);

    // 4) zero entropy accumulators
    zero4_kernel<<<1, TB>>>(ent);

    // 5) fused attention + entropy -> cs fp16 (cp.async double-buffered)
    attn_mma_kernel<<<dim3(TS / 64, TH, TB), 128, ATTN_SMEM>>>(
        qh2, kh2, vh2, cs, ent);

    // 6) transpose w_proj -> single fp16
    splitTs_kernel<<<dim3(TC / 32, TC / 32), dim3(32, 8)>>>(w_proj, wp, TC, TC);

    // 7) output projection (single fp16): [8192,1024] @ [1024,1024]
    gemm_s_kernel<<<dim3(TC / 128, BS / 128), 256, GEMM_S_SMEM>>>(
        cs, wp, out, BS, TC, TC);
}